// round 1
// baseline (speedup 1.0000x reference)
#include <cuda_runtime.h>
#include <cuda_bf16.h>
#include <math.h>

// Problem constants
#define BATCH   2
#define SEQ     1024
#define DMODEL  1024
#define NHEADS  16
#define DHEAD   64
#define DMAN    8
#define NTOK    (BATCH*SEQ)          // 2048
#define NBHT    (BATCH*NHEADS*SEQ)   // 32768
#define UDIM    80                   // 73 padded to 80
#define EPS_PSD 0.001f

// -------- device scratch (static, no allocations) --------
__device__ float g_q[NBHT*DHEAD];
__device__ float g_k[NBHT*DHEAD];
__device__ float g_v[NBHT*DHEAD];
__device__ float g_u[NBHT*UDIM];                 // row-major [n][80]
__device__ float g_wT[BATCH*NHEADS*UDIM*SEQ];    // transposed [bh][k][t]
__device__ float g_attn[NBHT*DHEAD];
__device__ float g_a2[NTOK*DMODEL];

// ============================================================
// Tiled SGEMM: C = A(MxK) * B(KxN), row-major. 128x128x16 tile,
// 256 threads, 8x8 per thread.
// MODE 0: plain row-major C.
// MODE 1: head-scatter: C[row,col] -> dst[((b*H+h)*T+t)*64+d]
// ============================================================
template<int MODE>
__global__ __launch_bounds__(256)
void gemm128(const float* __restrict__ A, const float* __restrict__ B,
             float* __restrict__ C, int M, int N, int K)
{
    __shared__ float As[16][132];
    __shared__ float Bs[16][132];

    int tid = threadIdx.x;
    int tx = tid & 15, ty = tid >> 4;
    int m0 = blockIdx.y * 128, n0 = blockIdx.x * 128;

    float acc[8][8];
    #pragma unroll
    for (int i = 0; i < 8; i++)
        #pragma unroll
        for (int j = 0; j < 8; j++) acc[i][j] = 0.0f;

    for (int k0 = 0; k0 < K; k0 += 16) {
        #pragma unroll
        for (int r = 0; r < 2; r++) {
            int p = tid + 256*r;
            // A: 128 rows x 16 cols, load float4 along K, store transposed
            int arow = p >> 2, ac4 = (p & 3) * 4;
            float4 av = *(const float4*)&A[(size_t)(m0+arow)*K + k0 + ac4];
            As[ac4+0][arow] = av.x; As[ac4+1][arow] = av.y;
            As[ac4+2][arow] = av.z; As[ac4+3][arow] = av.w;
            // B: 16 rows x 128 cols
            int brow = p >> 5, bc = (p & 31) * 4;
            float4 bv = *(const float4*)&B[(size_t)(k0+brow)*N + n0 + bc];
            *(float4*)&Bs[brow][bc] = bv;
        }
        __syncthreads();
        #pragma unroll
        for (int kk = 0; kk < 16; kk++) {
            float a[8], b[8];
            *(float4*)&a[0] = *(const float4*)&As[kk][ty*8];
            *(float4*)&a[4] = *(const float4*)&As[kk][ty*8+4];
            *(float4*)&b[0] = *(const float4*)&Bs[kk][tx*8];
            *(float4*)&b[4] = *(const float4*)&Bs[kk][tx*8+4];
            #pragma unroll
            for (int i = 0; i < 8; i++)
                #pragma unroll
                for (int j = 0; j < 8; j++)
                    acc[i][j] = fmaf(a[i], b[j], acc[i][j]);
        }
        __syncthreads();
    }

    int col = n0 + tx*8;
    #pragma unroll
    for (int i = 0; i < 8; i++) {
        int row = m0 + ty*8 + i;
        float4 v0 = make_float4(acc[i][0], acc[i][1], acc[i][2], acc[i][3]);
        float4 v1 = make_float4(acc[i][4], acc[i][5], acc[i][6], acc[i][7]);
        if (MODE == 0) {
            float* dst = C + (size_t)row*N + col;
            *(float4*)dst = v0; *(float4*)(dst+4) = v1;
        } else {
            // row = b*SEQ + t ; col = h*64 + d  (col is 8-aligned, same h for 8)
            int b = row >> 10, t = row & 1023;
            int h = col >> 6, d = col & 63;
            float* dst = C + ((size_t)((b*NHEADS + h)*SEQ + t))*DHEAD + d;
            *(float4*)dst = v0; *(float4*)(dst+4) = v1;
        }
    }
}

// ============================================================
// RoPE in-place on q and k  (layout [bh][t][64])
// pair (i, i+32), angle = t * 10000^(-i/32)
// ============================================================
__global__ void rope_kernel(float* __restrict__ q, float* __restrict__ k)
{
    int idx = blockIdx.x * blockDim.x + threadIdx.x;   // NBHT*32 threads
    if (idx >= NBHT*32) return;
    int i = idx & 31;
    int n = idx >> 5;             // bh*SEQ + t
    int t = n & 1023;
    float inv = (float)(1.0 / pow(10000.0, (double)i / 32.0));
    float ang = (float)t * inv;
    float s, c;
    sincosf(ang, &s, &c);
    size_t base = (size_t)n * DHEAD;
    float q1 = q[base+i], q2 = q[base+i+32];
    q[base+i]    = q1*c - q2*s;
    q[base+i+32] = q1*s + q2*c;
    float k1 = k[base+i], k2 = k[base+i+32];
    k[base+i]    = k1*c - k2*s;
    k[base+i+32] = k1*s + k2*c;
}

// ============================================================
// Feature kernel: per token build u[t] (80) and w[s] (80, transposed store)
// u = [2*Gq, -G_flat, -qGq, 0...] ; w = [k_m, kk_flat, 1, 0...]
// ============================================================
__global__ void feature_kernel(const float* __restrict__ q, const float* __restrict__ k,
                               const float* __restrict__ Wqm, const float* __restrict__ Wkm,
                               const float* __restrict__ Wm,
                               float* __restrict__ u, float* __restrict__ wT)
{
    __shared__ float sQ[64][65];
    __shared__ float sK[64][65];
    __shared__ float sWqm[512], sWkm[512], sWm[512];

    int tid = threadIdx.x;           // 64 threads
    int n0 = blockIdx.x * 64;

    for (int p = tid; p < 512; p += 64) {
        sWqm[p] = Wqm[p]; sWkm[p] = Wkm[p]; sWm[p] = Wm[p];
    }
    for (int p = tid; p < 64*64; p += 64) {
        sQ[p>>6][p&63] = q[(size_t)n0*64 + p];
        sK[p>>6][p&63] = k[(size_t)n0*64 + p];
    }
    __syncthreads();

    int n  = n0 + tid;
    int bh = n >> 10, t = n & 1023;

    float qm[8], km[8];
    #pragma unroll
    for (int m = 0; m < 8; m++) { qm[m] = 0.f; km[m] = 0.f; }
    for (int d = 0; d < 64; d++) {
        float qd = sQ[tid][d], kd = sK[tid][d];
        #pragma unroll
        for (int m = 0; m < 8; m++) {
            qm[m] = fmaf(qd, sWqm[d*8+m], qm[m]);
            km[m] = fmaf(kd, sWkm[d*8+m], km[m]);
        }
    }
    #pragma unroll
    for (int m = 0; m < 8; m++) {
        qm[m] = 1.0f / (1.0f + expf(-qm[m]));
        km[m] = 1.0f / (1.0f + expf(-km[m]));
    }

    // A[n] = sum_m qm[m]*Wm[m][n]   (A reshaped 8x8: A[d][e] = Avec[d*8+e])
    float A[64];
    #pragma unroll
    for (int nn = 0; nn < 64; nn++) {
        float s = 0.f;
        #pragma unroll
        for (int m = 0; m < 8; m++) s = fmaf(qm[m], sWm[m*64+nn], s);
        A[nn] = s;
    }

    float* urow = u + (size_t)n * UDIM;
    float Gq[8];
    #pragma unroll
    for (int d = 0; d < 8; d++) Gq[d] = 0.f;
    #pragma unroll
    for (int d = 0; d < 8; d++) {
        #pragma unroll
        for (int f = 0; f < 8; f++) {
            float g = 0.f;
            #pragma unroll
            for (int e = 0; e < 8; e++) g = fmaf(A[d*8+e], A[f*8+e], g);
            if (d == f) g += EPS_PSD;
            Gq[d] = fmaf(g, qm[f], Gq[d]);
            urow[8 + d*8 + f] = -g;
        }
    }
    float qGq = 0.f;
    #pragma unroll
    for (int d = 0; d < 8; d++) {
        qGq = fmaf(Gq[d], qm[d], qGq);
        urow[d] = 2.0f * Gq[d];
    }
    urow[72] = -qGq;
    #pragma unroll
    for (int p = 73; p < 80; p++) urow[p] = 0.f;

    // w transposed: wT[bh][kdim][t]
    float* wcol = wT + (size_t)bh * UDIM * SEQ + t;
    #pragma unroll
    for (int d = 0; d < 8; d++) wcol[(size_t)d * SEQ] = km[d];
    #pragma unroll
    for (int d = 0; d < 8; d++)
        #pragma unroll
        for (int f = 0; f < 8; f++)
            wcol[(size_t)(8 + d*8 + f) * SEQ] = km[d]*km[f];
    wcol[(size_t)72 * SEQ] = 1.0f;
    #pragma unroll
    for (int p = 73; p < 80; p++) wcol[(size_t)p * SEQ] = 0.f;
}

// ============================================================
// Flash attention: scores = min(u.w, 0)/temp, causal, PV accumulate.
// BR=BC=64, 256 threads, 4x4 register tile per thread.
// ============================================================
#define SU_STRIDE 84
#define SP_STRIDE 68
#define FLASH_SMEM ((64*SU_STRIDE + UDIM*64 + 64*64 + 64*SP_STRIDE) * 4)

__global__ __launch_bounds__(256)
void flash_kernel(const float* __restrict__ U, const float* __restrict__ Wt,
                  const float* __restrict__ V, float* __restrict__ O,
                  const float* __restrict__ temperature)
{
    extern __shared__ float sm[];
    float* sU = sm;                        // [64][84]
    float* sW = sU + 64*SU_STRIDE;         // [80][64]  (k-major)
    float* sV = sW + UDIM*64;              // [64][64]
    float* sP = sV + 64*64;                // [64][68]

    int bh  = blockIdx.y;
    int ib  = (gridDim.x - 1) - blockIdx.x;   // heaviest tiles launch first
    int tid = threadIdx.x;
    int tr = tid >> 4, tc = tid & 15;

    float inv_temp = 1.0f / fmaxf(temperature[0], 0.1f);

    // load U tile (row-major, stride-84 in smem)
    const float* Ubase = U + (size_t)(bh*SEQ + ib*64) * UDIM;
    for (int p = tid; p < 64*20; p += 256) {
        int r = p / 20, k4 = (p % 20) * 4;
        *(float4*)&sU[r*SU_STRIDE + k4] = *(const float4*)&Ubase[r*UDIM + k4];
    }

    float m_i[4], l_i[4], accO[4][4];
    #pragma unroll
    for (int i = 0; i < 4; i++) {
        m_i[i] = -INFINITY; l_i[i] = 0.f;
        #pragma unroll
        for (int j = 0; j < 4; j++) accO[i][j] = 0.f;
    }

    for (int jb = 0; jb <= ib; jb++) {
        __syncthreads();   // prior iteration done with sW/sV/sP (also covers sU load)
        // load W tile: wT is [bh][k][t] -> direct coalesced copy, k-major smem
        const float* Wbase = Wt + (size_t)bh * UDIM * SEQ + jb*64;
        for (int p = tid; p < UDIM*16; p += 256) {
            int kk = p >> 4, s4 = (p & 15) * 4;
            *(float4*)&sW[kk*64 + s4] = *(const float4*)&Wbase[(size_t)kk*SEQ + s4];
        }
        // load V tile
        const float* Vbase = V + (size_t)(bh*SEQ + jb*64) * DHEAD;
        for (int p = tid; p < 64*16; p += 256)
            ((float4*)sV)[p] = ((const float4*)Vbase)[p];
        __syncthreads();

        // ---- S = U . W  (4x4 per thread) ----
        float acc[4][4];
        #pragma unroll
        for (int i = 0; i < 4; i++)
            #pragma unroll
            for (int j = 0; j < 4; j++) acc[i][j] = 0.f;

        for (int kk = 0; kk < UDIM; kk += 4) {
            float4 a[4];
            #pragma unroll
            for (int i = 0; i < 4; i++)
                a[i] = *(const float4*)&sU[(tr*4+i)*SU_STRIDE + kk];
            #pragma unroll
            for (int c = 0; c < 4; c++) {
                float4 wv = *(const float4*)&sW[(kk+c)*64 + tc*4];
                #pragma unroll
                for (int i = 0; i < 4; i++) {
                    float av = ((const float*)&a[i])[c];
                    acc[i][0] = fmaf(av, wv.x, acc[i][0]);
                    acc[i][1] = fmaf(av, wv.y, acc[i][1]);
                    acc[i][2] = fmaf(av, wv.z, acc[i][2]);
                    acc[i][3] = fmaf(av, wv.w, acc[i][3]);
                }
            }
        }

        // ---- scores + causal mask ----
        bool diag = (jb == ib);
        #pragma unroll
        for (int i = 0; i < 4; i++) {
            int t_g = ib*64 + tr*4 + i;
            #pragma unroll
            for (int j = 0; j < 4; j++) {
                float sc = fminf(acc[i][j], 0.0f) * inv_temp;
                if (diag && (jb*64 + tc*4 + j) > t_g) sc = -INFINITY;
                acc[i][j] = sc;
            }
        }

        // ---- online softmax (reduce over 16 tx lanes via shfl) ----
        #pragma unroll
        for (int i = 0; i < 4; i++) {
            float mrow = fmaxf(fmaxf(acc[i][0], acc[i][1]), fmaxf(acc[i][2], acc[i][3]));
            #pragma unroll
            for (int off = 8; off; off >>= 1)
                mrow = fmaxf(mrow, __shfl_xor_sync(0xffffffffu, mrow, off));
            float mnew = fmaxf(m_i[i], mrow);
            float corr = expf(m_i[i] - mnew);
            float psum = 0.f;
            #pragma unroll
            for (int j = 0; j < 4; j++) {
                float p = expf(acc[i][j] - mnew);
                acc[i][j] = p; psum += p;
            }
            #pragma unroll
            for (int off = 8; off; off >>= 1)
                psum += __shfl_xor_sync(0xffffffffu, psum, off);
            l_i[i] = l_i[i]*corr + psum;
            m_i[i] = mnew;
            #pragma unroll
            for (int j = 0; j < 4; j++) accO[i][j] *= corr;
            #pragma unroll
            for (int j = 0; j < 4; j++)
                sP[(tr*4+i)*SP_STRIDE + tc*4 + j] = acc[i][j];
        }
        __syncthreads();

        // ---- O += P @ V ----
        for (int s = 0; s < 64; s += 4) {
            float4 p[4];
            #pragma unroll
            for (int i = 0; i < 4; i++)
                p[i] = *(const float4*)&sP[(tr*4+i)*SP_STRIDE + s];
            #pragma unroll
            for (int c = 0; c < 4; c++) {
                float4 vv = *(const float4*)&sV[(s+c)*64 + tc*4];
                #pragma unroll
                for (int i = 0; i < 4; i++) {
                    float pv = ((const float*)&p[i])[c];
                    accO[i][0] = fmaf(pv, vv.x, accO[i][0]);
                    accO[i][1] = fmaf(pv, vv.y, accO[i][1]);
                    accO[i][2] = fmaf(pv, vv.z, accO[i][2]);
                    accO[i][3] = fmaf(pv, vv.w, accO[i][3]);
                }
            }
        }
    }

    #pragma unroll
    for (int i = 0; i < 4; i++) {
        float inv_l = 1.0f / l_i[i];
        int t_g = ib*64 + tr*4 + i;
        float4 o = make_float4(accO[i][0]*inv_l, accO[i][1]*inv_l,
                               accO[i][2]*inv_l, accO[i][3]*inv_l);
        *(float4*)&O[((size_t)(bh*SEQ + t_g))*DHEAD + tc*4] = o;
    }
}

// ============================================================
// Repack attn [bh][t][d] -> token-major [b*T+t][h*64+d]
// ============================================================
__global__ void repack_kernel(const float* __restrict__ attn, float* __restrict__ a2)
{
    int idx = blockIdx.x * blockDim.x + threadIdx.x;
    if (idx >= NBHT*DHEAD) return;
    int d  = idx & 63;
    int bht = idx >> 6;
    int t  = bht & 1023;
    int bh = bht >> 10;
    int h  = bh & 15, b = bh >> 4;
    a2[((size_t)(b*SEQ + t))*DMODEL + h*DHEAD + d] = attn[idx];
}

// ============================================================
extern "C" void kernel_launch(void* const* d_in, const int* in_sizes, int n_in,
                              void* d_out, int out_size)
{
    (void)in_sizes; (void)n_in; (void)out_size;
    const float* x    = (const float*)d_in[0];
    const float* Wq   = (const float*)d_in[1];
    const float* Wk   = (const float*)d_in[2];
    const float* Wv   = (const float*)d_in[3];
    const float* Wo   = (const float*)d_in[4];
    const float* Wqm  = (const float*)d_in[5];
    const float* Wkm  = (const float*)d_in[6];
    const float* Wm   = (const float*)d_in[7];
    const float* temp = (const float*)d_in[8];

    float *q, *k, *v, *u, *wT, *attn, *a2;
    cudaGetSymbolAddress((void**)&q,    g_q);
    cudaGetSymbolAddress((void**)&k,    g_k);
    cudaGetSymbolAddress((void**)&v,    g_v);
    cudaGetSymbolAddress((void**)&u,    g_u);
    cudaGetSymbolAddress((void**)&wT,   g_wT);
    cudaGetSymbolAddress((void**)&attn, g_attn);
    cudaGetSymbolAddress((void**)&a2,   g_a2);

    dim3 gQKV(DMODEL/128, NTOK/128);   // (8, 16)
    gemm128<1><<<gQKV, 256>>>(x, Wq, q, NTOK, DMODEL, DMODEL);
    gemm128<1><<<gQKV, 256>>>(x, Wk, k, NTOK, DMODEL, DMODEL);
    gemm128<1><<<gQKV, 256>>>(x, Wv, v, NTOK, DMODEL, DMODEL);

    rope_kernel<<<(NBHT*32)/256, 256>>>(q, k);

    feature_kernel<<<NBHT/64, 64>>>(q, k, Wqm, Wkm, Wm, u, wT);

    cudaFuncSetAttribute(flash_kernel,
                         cudaFuncAttributeMaxDynamicSharedMemorySize, FLASH_SMEM);
    flash_kernel<<<dim3(SEQ/64, BATCH*NHEADS), 256, FLASH_SMEM>>>(u, wT, v, attn, temp);

    repack_kernel<<<(NBHT*DHEAD)/256, 256>>>(attn, a2);

    gemm128<0><<<dim3(DMODEL/128, NTOK/128), 256>>>(a2, Wo, (float*)d_out,
                                                    NTOK, DMODEL, DMODEL);
}

// round 3
// speedup vs baseline: 1.6521x; 1.6521x over previous
#include <cuda_runtime.h>
#include <cuda_bf16.h>
#include <math.h>
#include <stdint.h>

// Problem constants
#define BATCH   2
#define SEQ     1024
#define DMODEL  1024
#define NHEADS  16
#define DHEAD   64
#define NTOK    (BATCH*SEQ)          // 2048
#define NBHT    (BATCH*NHEADS*SEQ)   // 32768
#define UDIM    80                   // 73 padded to 80
#define EPS_PSD 0.001f

// -------- device scratch (static, no allocations) --------
__device__ float g_q[NBHT*DHEAD];
__device__ float g_k[NBHT*DHEAD];
__device__ float g_v[NBHT*DHEAD];
__device__ float g_u[NBHT*UDIM];                 // row-major [n][80]
__device__ float g_wT[BATCH*NHEADS*UDIM*SEQ];    // transposed [bh][k][t]
__device__ float g_attn[NBHT*DHEAD];

// bf16 split operands
__device__ __nv_bfloat16 g_xh[NTOK*DMODEL];
__device__ __nv_bfloat16 g_xl[NTOK*DMODEL];
__device__ __nv_bfloat16 g_wth[4*DMODEL*DMODEL]; // Wq,Wk,Wv,Wo transposed [n][k]
__device__ __nv_bfloat16 g_wtl[4*DMODEL*DMODEL];
__device__ __nv_bfloat16 g_a2h[NTOK*DMODEL];
__device__ __nv_bfloat16 g_a2l[NTOK*DMODEL];

// ============================================================
// PTX helpers (sm_80-level: mma.sync bf16, ldmatrix, cp.async)
// ============================================================
__device__ __forceinline__ uint32_t smem_u32(const void* p) {
    uint32_t a;
    asm("{ .reg .u64 t; cvta.to.shared.u64 t, %1; cvt.u32.u64 %0, t; }" : "=r"(a) : "l"(p));
    return a;
}

__device__ __forceinline__ void ldmatrix_x4(uint32_t* r, uint32_t addr) {
    asm volatile("ldmatrix.sync.aligned.m8n8.x4.shared.b16 {%0,%1,%2,%3}, [%4];"
        : "=r"(r[0]), "=r"(r[1]), "=r"(r[2]), "=r"(r[3]) : "r"(addr));
}
__device__ __forceinline__ void ldmatrix_x2(uint32_t* r, uint32_t addr) {
    asm volatile("ldmatrix.sync.aligned.m8n8.x2.shared.b16 {%0,%1}, [%2];"
        : "=r"(r[0]), "=r"(r[1]) : "r"(addr));
}
__device__ __forceinline__ void mma16816(float* c, const uint32_t* a, const uint32_t* b) {
    asm volatile("mma.sync.aligned.m16n8k16.row.col.f32.bf16.bf16.f32 "
        "{%0,%1,%2,%3}, {%4,%5,%6,%7}, {%8,%9}, {%0,%1,%2,%3};"
        : "+f"(c[0]), "+f"(c[1]), "+f"(c[2]), "+f"(c[3])
        : "r"(a[0]), "r"(a[1]), "r"(a[2]), "r"(a[3]), "r"(b[0]), "r"(b[1]));
}

#define CP_ASYNC16(saddr, gptr) \
    asm volatile("cp.async.cg.shared.global [%0], [%1], 16;" \
        :: "r"(saddr), "l"(gptr) : "memory")
#define CP_COMMIT() asm volatile("cp.async.commit_group;" ::: "memory")
#define CP_WAIT(N)  asm volatile("cp.async.wait_group %0;" :: "n"(N) : "memory")

// ============================================================
// Conversion kernels
// ============================================================
__global__ void xconv_kernel(const float* __restrict__ x,
                             __nv_bfloat16* __restrict__ xh,
                             __nv_bfloat16* __restrict__ xl)
{
    int i = blockIdx.x * blockDim.x + threadIdx.x;
    if (i >= NTOK*DMODEL) return;
    float v = x[i];
    __nv_bfloat16 h = __float2bfloat16(v);
    xh[i] = h;
    xl[i] = __float2bfloat16(v - __bfloat162float(h));
}

// transpose + split: W[k][n] (1024x1024) -> Wt[n][k] hi/lo
__global__ void wconv_kernel(const float* __restrict__ W0, const float* __restrict__ W1,
                             const float* __restrict__ W2, const float* __restrict__ W3,
                             __nv_bfloat16* __restrict__ th, __nv_bfloat16* __restrict__ tl)
{
    __shared__ float s[32][33];
    const float* W = (blockIdx.z == 0) ? W0 : (blockIdx.z == 1) ? W1
                   : (blockIdx.z == 2) ? W2 : W3;
    size_t zoff = (size_t)blockIdx.z * DMODEL * DMODEL;
    int n0 = blockIdx.x * 32, k0 = blockIdx.y * 32;
    int tx = threadIdx.x, ty = threadIdx.y;   // 32 x 8
    #pragma unroll
    for (int j = 0; j < 4; j++)
        s[ty + j*8][tx] = W[(size_t)(k0 + ty + j*8)*DMODEL + n0 + tx];
    __syncthreads();
    #pragma unroll
    for (int j = 0; j < 4; j++) {
        float v = s[tx][ty + j*8];
        __nv_bfloat16 h = __float2bfloat16(v);
        size_t o = zoff + (size_t)(n0 + ty + j*8)*DMODEL + k0 + tx;
        th[o] = h;
        tl[o] = __float2bfloat16(v - __bfloat162float(h));
    }
}

// ============================================================
// mma.sync bf16x3 GEMM: C(2048x1024 f32) = A * B^T
// A bf16 hi/lo row-major [M][K]; B bf16 hi/lo [N][K] (K-major).
// 128x128 CTA tile, 8 warps (2m x 4n), warp = 64x32 via 4x4 m16n8k16.
// cp.async double-buffered K chunks of 32.
// MODE 0: plain row-major C.  MODE 1: QKV head-scatter.
// ============================================================
#define KC 32
#define ROW_STRIDE 40                      // bf16 elems per smem row (80B, conflict-free)
#define MAT_BYTES (128*ROW_STRIDE*2)       // 10240
#define BUF_BYTES (4*MAT_BYTES)            // 40960 (Ah, Al, Bh, Bl)
#define GEMM_SMEM (2*BUF_BYTES)            // 81920

template<int MODE>
__global__ __launch_bounds__(256, 1)
void mma_gemm(const __nv_bfloat16* __restrict__ Ah, const __nv_bfloat16* __restrict__ Al,
              const __nv_bfloat16* __restrict__ Bh, const __nv_bfloat16* __restrict__ Bl,
              float* __restrict__ C)
{
    extern __shared__ char smem[];
    uint32_t sbase = smem_u32(smem);
    int tid = threadIdx.x, wid = tid >> 5, lane = tid & 31;
    int n0 = blockIdx.x * 128, m0 = blockIdx.y * 128;

    // loader role: 64 threads per matrix (Ah, Al, Bh, Bl)
    int mat = tid >> 6;
    int tp  = tid & 63;
    const __nv_bfloat16* gsrc =
        (mat == 0) ? Ah + (size_t)m0*DMODEL :
        (mat == 1) ? Al + (size_t)m0*DMODEL :
        (mat == 2) ? Bh + (size_t)n0*DMODEL :
                     Bl + (size_t)n0*DMODEL;
    uint32_t s_mat = sbase + mat*MAT_BYTES;

    int warp_m = wid & 1, warp_n = wid >> 1;

    float acc[4][4][4];
    #pragma unroll
    for (int a = 0; a < 4; a++)
        #pragma unroll
        for (int b = 0; b < 4; b++)
            #pragma unroll
            for (int c = 0; c < 4; c++) acc[a][b][c] = 0.f;

    // ---- issue chunk 0 ----
    {
        const __nv_bfloat16* g = gsrc;
        #pragma unroll
        for (int it = 0; it < 8; it++) {
            int idx = tp + it*64;              // 0..511
            int row = idx >> 2, c4 = idx & 3;
            CP_ASYNC16(s_mat + row*(ROW_STRIDE*2) + c4*16,
                       g + (size_t)row*DMODEL + c4*8);
        }
        CP_COMMIT();
    }

    for (int c = 0; c < DMODEL/KC; c++) {
        int buf = c & 1;
        if (c + 1 < DMODEL/KC) {
            const __nv_bfloat16* g = gsrc + (c + 1)*KC;
            uint32_t sb = s_mat + (buf ^ 1)*BUF_BYTES;
            #pragma unroll
            for (int it = 0; it < 8; it++) {
                int idx = tp + it*64;
                int row = idx >> 2, c4 = idx & 3;
                CP_ASYNC16(sb + row*(ROW_STRIDE*2) + c4*16,
                           g + (size_t)row*DMODEL + c4*8);
            }
            CP_COMMIT();
            CP_WAIT(1);
        } else {
            CP_WAIT(0);
        }
        __syncthreads();

        // ---- compute chunk c from buf ----
        uint32_t b_off = sbase + buf*BUF_BYTES;
        #pragma unroll
        for (int ks = 0; ks < 2; ks++) {
            int k0 = ks * 16;
            uint32_t a_h[4][4], a_l[4][4], b_h[4][2], b_l[4][2];
            #pragma unroll
            for (int mt = 0; mt < 4; mt++) {
                int row = warp_m*64 + mt*16 + (lane & 15);
                uint32_t col = k0 + ((lane >> 4) << 3);
                uint32_t off = b_off + (row*ROW_STRIDE + col)*2;
                ldmatrix_x4(a_h[mt], off);
                ldmatrix_x4(a_l[mt], off + MAT_BYTES);
            }
            #pragma unroll
            for (int nt = 0; nt < 4; nt++) {
                int row = warp_n*32 + nt*8 + (lane & 7);
                uint32_t col = k0 + (((lane >> 3) & 1) << 3);
                uint32_t off = b_off + (row*ROW_STRIDE + col)*2;
                ldmatrix_x2(b_h[nt], off + 2*MAT_BYTES);
                ldmatrix_x2(b_l[nt], off + 3*MAT_BYTES);
            }
            #pragma unroll
            for (int mt = 0; mt < 4; mt++)
                #pragma unroll
                for (int nt = 0; nt < 4; nt++) {
                    mma16816(acc[mt][nt], a_h[mt], b_h[nt]);
                    mma16816(acc[mt][nt], a_h[mt], b_l[nt]);
                    mma16816(acc[mt][nt], a_l[mt], b_h[nt]);
                }
        }
        __syncthreads();
    }

    // ---- epilogue ----
    int qrow = lane >> 2, qcol = (lane & 3) * 2;
    #pragma unroll
    for (int mt = 0; mt < 4; mt++) {
        #pragma unroll
        for (int nt = 0; nt < 4; nt++) {
            int row0 = m0 + warp_m*64 + mt*16 + qrow;
            int col  = n0 + warp_n*32 + nt*8 + qcol;
            float2 v0 = make_float2(acc[mt][nt][0], acc[mt][nt][1]);
            float2 v1 = make_float2(acc[mt][nt][2], acc[mt][nt][3]);
            if (MODE == 0) {
                *(float2*)&C[(size_t)row0*DMODEL + col] = v0;
                *(float2*)&C[(size_t)(row0 + 8)*DMODEL + col] = v1;
            } else {
                int h = col >> 6, d = col & 63;
                int b0 = row0 >> 10, t0 = row0 & 1023;
                *(float2*)&C[((size_t)((b0*NHEADS + h)*SEQ + t0))*DHEAD + d] = v0;
                int r1 = row0 + 8;
                int b1 = r1 >> 10, t1 = r1 & 1023;
                *(float2*)&C[((size_t)((b1*NHEADS + h)*SEQ + t1))*DHEAD + d] = v1;
            }
        }
    }
}

// ============================================================
// RoPE in-place on q and k  (layout [bh][t][64])
// ============================================================
__global__ void rope_kernel(float* __restrict__ q, float* __restrict__ k)
{
    int idx = blockIdx.x * blockDim.x + threadIdx.x;
    if (idx >= NBHT*32) return;
    int i = idx & 31;
    int n = idx >> 5;
    int t = n & 1023;
    float inv = (float)(1.0 / pow(10000.0, (double)i / 32.0));
    float ang = (float)t * inv;
    float s, c;
    sincosf(ang, &s, &c);
    size_t base = (size_t)n * DHEAD;
    float q1 = q[base+i], q2 = q[base+i+32];
    q[base+i]    = q1*c - q2*s;
    q[base+i+32] = q1*s + q2*c;
    float k1 = k[base+i], k2 = k[base+i+32];
    k[base+i]    = k1*c - k2*s;
    k[base+i+32] = k1*s + k2*c;
}

// ============================================================
// Feature kernel: per token build u[t] (80) and w[s] (80, transposed)
// ============================================================
__global__ void feature_kernel(const float* __restrict__ q, const float* __restrict__ k,
                               const float* __restrict__ Wqm, const float* __restrict__ Wkm,
                               const float* __restrict__ Wm,
                               float* __restrict__ u, float* __restrict__ wT)
{
    __shared__ float sQ[64][65];
    __shared__ float sK[64][65];
    __shared__ float sWqm[512], sWkm[512], sWm[512];

    int tid = threadIdx.x;           // 64 threads
    int n0 = blockIdx.x * 64;

    for (int p = tid; p < 512; p += 64) {
        sWqm[p] = Wqm[p]; sWkm[p] = Wkm[p]; sWm[p] = Wm[p];
    }
    for (int p = tid; p < 64*64; p += 64) {
        sQ[p>>6][p&63] = q[(size_t)n0*64 + p];
        sK[p>>6][p&63] = k[(size_t)n0*64 + p];
    }
    __syncthreads();

    int n  = n0 + tid;
    int bh = n >> 10, t = n & 1023;

    float qm[8], km[8];
    #pragma unroll
    for (int m = 0; m < 8; m++) { qm[m] = 0.f; km[m] = 0.f; }
    for (int d = 0; d < 64; d++) {
        float qd = sQ[tid][d], kd = sK[tid][d];
        #pragma unroll
        for (int m = 0; m < 8; m++) {
            qm[m] = fmaf(qd, sWqm[d*8+m], qm[m]);
            km[m] = fmaf(kd, sWkm[d*8+m], km[m]);
        }
    }
    #pragma unroll
    for (int m = 0; m < 8; m++) {
        qm[m] = 1.0f / (1.0f + expf(-qm[m]));
        km[m] = 1.0f / (1.0f + expf(-km[m]));
    }

    float A[64];
    #pragma unroll
    for (int nn = 0; nn < 64; nn++) {
        float s = 0.f;
        #pragma unroll
        for (int m = 0; m < 8; m++) s = fmaf(qm[m], sWm[m*64+nn], s);
        A[nn] = s;
    }

    float* urow = u + (size_t)n * UDIM;
    float Gq[8];
    #pragma unroll
    for (int d = 0; d < 8; d++) Gq[d] = 0.f;
    #pragma unroll
    for (int d = 0; d < 8; d++) {
        #pragma unroll
        for (int f = 0; f < 8; f++) {
            float g = 0.f;
            #pragma unroll
            for (int e = 0; e < 8; e++) g = fmaf(A[d*8+e], A[f*8+e], g);
            if (d == f) g += EPS_PSD;
            Gq[d] = fmaf(g, qm[f], Gq[d]);
            urow[8 + d*8 + f] = -g;
        }
    }
    float qGq = 0.f;
    #pragma unroll
    for (int d = 0; d < 8; d++) {
        qGq = fmaf(Gq[d], qm[d], qGq);
        urow[d] = 2.0f * Gq[d];
    }
    urow[72] = -qGq;
    #pragma unroll
    for (int p = 73; p < 80; p++) urow[p] = 0.f;

    float* wcol = wT + (size_t)bh * UDIM * SEQ + t;
    #pragma unroll
    for (int d = 0; d < 8; d++) wcol[(size_t)d * SEQ] = km[d];
    #pragma unroll
    for (int d = 0; d < 8; d++)
        #pragma unroll
        for (int f = 0; f < 8; f++)
            wcol[(size_t)(8 + d*8 + f) * SEQ] = km[d]*km[f];
    wcol[(size_t)72 * SEQ] = 1.0f;
    #pragma unroll
    for (int p = 73; p < 80; p++) wcol[(size_t)p * SEQ] = 0.f;
}

// ============================================================
// Flash attention: scores = min(u.w, 0)/temp, causal, PV accumulate.
// ============================================================
#define SU_STRIDE 84
#define SP_STRIDE 68
#define FLASH_SMEM ((64*SU_STRIDE + UDIM*64 + 64*64 + 64*SP_STRIDE) * 4)

__global__ __launch_bounds__(256)
void flash_kernel(const float* __restrict__ U, const float* __restrict__ Wt,
                  const float* __restrict__ V, float* __restrict__ O,
                  const float* __restrict__ temperature)
{
    extern __shared__ float sm[];
    float* sU = sm;                        // [64][84]
    float* sW = sU + 64*SU_STRIDE;         // [80][64]  (k-major)
    float* sV = sW + UDIM*64;              // [64][64]
    float* sP = sV + 64*64;                // [64][68]

    int bh  = blockIdx.y;
    int ib  = (gridDim.x - 1) - blockIdx.x;
    int tid = threadIdx.x;
    int tr = tid >> 4, tc = tid & 15;

    float inv_temp = 1.0f / fmaxf(temperature[0], 0.1f);

    const float* Ubase = U + (size_t)(bh*SEQ + ib*64) * UDIM;
    for (int p = tid; p < 64*20; p += 256) {
        int r = p / 20, k4 = (p % 20) * 4;
        *(float4*)&sU[r*SU_STRIDE + k4] = *(const float4*)&Ubase[r*UDIM + k4];
    }

    float m_i[4], l_i[4], accO[4][4];
    #pragma unroll
    for (int i = 0; i < 4; i++) {
        m_i[i] = -INFINITY; l_i[i] = 0.f;
        #pragma unroll
        for (int j = 0; j < 4; j++) accO[i][j] = 0.f;
    }

    for (int jb = 0; jb <= ib; jb++) {
        __syncthreads();
        const float* Wbase = Wt + (size_t)bh * UDIM * SEQ + jb*64;
        for (int p = tid; p < UDIM*16; p += 256) {
            int kk = p >> 4, s4 = (p & 15) * 4;
            *(float4*)&sW[kk*64 + s4] = *(const float4*)&Wbase[(size_t)kk*SEQ + s4];
        }
        const float* Vbase = V + (size_t)(bh*SEQ + jb*64) * DHEAD;
        for (int p = tid; p < 64*16; p += 256)
            ((float4*)sV)[p] = ((const float4*)Vbase)[p];
        __syncthreads();

        float acc[4][4];
        #pragma unroll
        for (int i = 0; i < 4; i++)
            #pragma unroll
            for (int j = 0; j < 4; j++) acc[i][j] = 0.f;

        for (int kk = 0; kk < UDIM; kk += 4) {
            float4 a[4];
            #pragma unroll
            for (int i = 0; i < 4; i++)
                a[i] = *(const float4*)&sU[(tr*4+i)*SU_STRIDE + kk];
            #pragma unroll
            for (int c = 0; c < 4; c++) {
                float4 wv = *(const float4*)&sW[(kk+c)*64 + tc*4];
                #pragma unroll
                for (int i = 0; i < 4; i++) {
                    float av = ((const float*)&a[i])[c];
                    acc[i][0] = fmaf(av, wv.x, acc[i][0]);
                    acc[i][1] = fmaf(av, wv.y, acc[i][1]);
                    acc[i][2] = fmaf(av, wv.z, acc[i][2]);
                    acc[i][3] = fmaf(av, wv.w, acc[i][3]);
                }
            }
        }

        bool diag = (jb == ib);
        #pragma unroll
        for (int i = 0; i < 4; i++) {
            int t_g = ib*64 + tr*4 + i;
            #pragma unroll
            for (int j = 0; j < 4; j++) {
                float sc = fminf(acc[i][j], 0.0f) * inv_temp;
                if (diag && (jb*64 + tc*4 + j) > t_g) sc = -INFINITY;
                acc[i][j] = sc;
            }
        }

        #pragma unroll
        for (int i = 0; i < 4; i++) {
            float mrow = fmaxf(fmaxf(acc[i][0], acc[i][1]), fmaxf(acc[i][2], acc[i][3]));
            #pragma unroll
            for (int off = 8; off; off >>= 1)
                mrow = fmaxf(mrow, __shfl_xor_sync(0xffffffffu, mrow, off));
            float mnew = fmaxf(m_i[i], mrow);
            float corr = expf(m_i[i] - mnew);
            float psum = 0.f;
            #pragma unroll
            for (int j = 0; j < 4; j++) {
                float p = expf(acc[i][j] - mnew);
                acc[i][j] = p; psum += p;
            }
            #pragma unroll
            for (int off = 8; off; off >>= 1)
                psum += __shfl_xor_sync(0xffffffffu, psum, off);
            l_i[i] = l_i[i]*corr + psum;
            m_i[i] = mnew;
            #pragma unroll
            for (int j = 0; j < 4; j++) accO[i][j] *= corr;
            #pragma unroll
            for (int j = 0; j < 4; j++)
                sP[(tr*4+i)*SP_STRIDE + tc*4 + j] = acc[i][j];
        }
        __syncthreads();

        for (int s = 0; s < 64; s += 4) {
            float4 p[4];
            #pragma unroll
            for (int i = 0; i < 4; i++)
                p[i] = *(const float4*)&sP[(tr*4+i)*SP_STRIDE + s];
            #pragma unroll
            for (int c = 0; c < 4; c++) {
                float4 vv = *(const float4*)&sV[(s+c)*64 + tc*4];
                #pragma unroll
                for (int i = 0; i < 4; i++) {
                    float pv = ((const float*)&p[i])[c];
                    accO[i][0] = fmaf(pv, vv.x, accO[i][0]);
                    accO[i][1] = fmaf(pv, vv.y, accO[i][1]);
                    accO[i][2] = fmaf(pv, vv.z, accO[i][2]);
                    accO[i][3] = fmaf(pv, vv.w, accO[i][3]);
                }
            }
        }
    }

    #pragma unroll
    for (int i = 0; i < 4; i++) {
        float inv_l = 1.0f / l_i[i];
        int t_g = ib*64 + tr*4 + i;
        float4 o = make_float4(accO[i][0]*inv_l, accO[i][1]*inv_l,
                               accO[i][2]*inv_l, accO[i][3]*inv_l);
        *(float4*)&O[((size_t)(bh*SEQ + t_g))*DHEAD + tc*4] = o;
    }
}

// ============================================================
// Repack attn [bh][t][d] -> token-major bf16 hi/lo [b*T+t][h*64+d]
// ============================================================
__global__ void repack_conv_kernel(const float* __restrict__ attn,
                                   __nv_bfloat16* __restrict__ ah,
                                   __nv_bfloat16* __restrict__ al)
{
    int idx = blockIdx.x * blockDim.x + threadIdx.x;
    if (idx >= NBHT*DHEAD) return;
    int d  = idx & 63;
    int bht = idx >> 6;
    int t  = bht & 1023;
    int bh = bht >> 10;
    int h  = bh & 15, b = bh >> 4;
    float v = attn[idx];
    __nv_bfloat16 hv = __float2bfloat16(v);
    size_t o = ((size_t)(b*SEQ + t))*DMODEL + h*DHEAD + d;
    ah[o] = hv;
    al[o] = __float2bfloat16(v - __bfloat162float(hv));
}

// ============================================================
extern "C" void kernel_launch(void* const* d_in, const int* in_sizes, int n_in,
                              void* d_out, int out_size)
{
    (void)in_sizes; (void)n_in; (void)out_size;
    const float* x    = (const float*)d_in[0];
    const float* Wq   = (const float*)d_in[1];
    const float* Wk   = (const float*)d_in[2];
    const float* Wv   = (const float*)d_in[3];
    const float* Wo   = (const float*)d_in[4];
    const float* Wqm  = (const float*)d_in[5];
    const float* Wkm  = (const float*)d_in[6];
    const float* Wm   = (const float*)d_in[7];
    const float* temp = (const float*)d_in[8];

    float *q, *k, *v, *u, *wT, *attn;
    __nv_bfloat16 *xh, *xl, *wth, *wtl, *a2h, *a2l;
    cudaGetSymbolAddress((void**)&q,    g_q);
    cudaGetSymbolAddress((void**)&k,    g_k);
    cudaGetSymbolAddress((void**)&v,    g_v);
    cudaGetSymbolAddress((void**)&u,    g_u);
    cudaGetSymbolAddress((void**)&wT,   g_wT);
    cudaGetSymbolAddress((void**)&attn, g_attn);
    cudaGetSymbolAddress((void**)&xh,   g_xh);
    cudaGetSymbolAddress((void**)&xl,   g_xl);
    cudaGetSymbolAddress((void**)&wth,  g_wth);
    cudaGetSymbolAddress((void**)&wtl,  g_wtl);
    cudaGetSymbolAddress((void**)&a2h,  g_a2h);
    cudaGetSymbolAddress((void**)&a2l,  g_a2l);

    cudaFuncSetAttribute(mma_gemm<0>, cudaFuncAttributeMaxDynamicSharedMemorySize, GEMM_SMEM);
    cudaFuncSetAttribute(mma_gemm<1>, cudaFuncAttributeMaxDynamicSharedMemorySize, GEMM_SMEM);
    cudaFuncSetAttribute(flash_kernel, cudaFuncAttributeMaxDynamicSharedMemorySize, FLASH_SMEM);

    // operand conversion
    wconv_kernel<<<dim3(32, 32, 4), dim3(32, 8)>>>(Wq, Wk, Wv, Wo, wth, wtl);
    xconv_kernel<<<(NTOK*DMODEL)/256, 256>>>(x, xh, xl);

    // QKV projections (mma.sync bf16x3, head-scatter epilogue)
    dim3 g128(DMODEL/128, NTOK/128);   // (8, 16)
    size_t WSZ = (size_t)DMODEL*DMODEL;
    mma_gemm<1><<<g128, 256, GEMM_SMEM>>>(xh, xl, wth + 0*WSZ, wtl + 0*WSZ, q);
    mma_gemm<1><<<g128, 256, GEMM_SMEM>>>(xh, xl, wth + 1*WSZ, wtl + 1*WSZ, k);
    mma_gemm<1><<<g128, 256, GEMM_SMEM>>>(xh, xl, wth + 2*WSZ, wtl + 2*WSZ, v);

    rope_kernel<<<(NBHT*32)/256, 256>>>(q, k);

    feature_kernel<<<NBHT/64, 64>>>(q, k, Wqm, Wkm, Wm, u, wT);

    flash_kernel<<<dim3(SEQ/64, BATCH*NHEADS), 256, FLASH_SMEM>>>(u, wT, v, attn, temp);

    repack_conv_kernel<<<(NBHT*DHEAD)/256, 256>>>(attn, a2h, a2l);

    mma_gemm<0><<<g128, 256, GEMM_SMEM>>>(a2h, a2l, wth + 3*WSZ, wtl + 3*WSZ, (float*)d_out);
}

// round 4
// speedup vs baseline: 2.4295x; 1.4705x over previous
#include <cuda_runtime.h>
#include <cuda_bf16.h>
#include <math.h>
#include <stdint.h>

// Problem constants
#define BATCH   2
#define SEQ     1024
#define DMODEL  1024
#define NHEADS  16
#define DHEAD   64
#define NTOK    (BATCH*SEQ)          // 2048
#define NBHT    (BATCH*NHEADS*SEQ)   // 32768
#define UDIM    80                   // 73 padded to 80
#define EPS_PSD 0.001f

// -------- device scratch (static, no allocations) --------
__device__ float g_q[NBHT*DHEAD];
__device__ float g_k[NBHT*DHEAD];

__device__ __nv_bfloat16 g_xh[NTOK*DMODEL];
__device__ __nv_bfloat16 g_xl[NTOK*DMODEL];
__device__ __nv_bfloat16 g_wth[4*DMODEL*DMODEL]; // Wq,Wk,Wv,Wo transposed [n][k]
__device__ __nv_bfloat16 g_wtl[4*DMODEL*DMODEL];

__device__ __nv_bfloat16 g_vh[NBHT*DHEAD];       // V bf16 hi/lo [bh][t][d]
__device__ __nv_bfloat16 g_vl[NBHT*DHEAD];

__device__ __nv_bfloat16 g_uh[NBHT*UDIM];        // u rows bf16 hi/lo [n][80]
__device__ __nv_bfloat16 g_ul[NBHT*UDIM];
__device__ __nv_bfloat16 g_wh[NBHT*UDIM];        // w rows bf16 hi/lo [n][80]
__device__ __nv_bfloat16 g_wl[NBHT*UDIM];

__device__ __nv_bfloat16 g_a2h[NTOK*DMODEL];     // attention out, token-major
__device__ __nv_bfloat16 g_a2l[NTOK*DMODEL];

// ============================================================
// PTX helpers
// ============================================================
__device__ __forceinline__ uint32_t smem_u32(const void* p) {
    uint32_t a;
    asm("{ .reg .u64 t; cvta.to.shared.u64 t, %1; cvt.u32.u64 %0, t; }" : "=r"(a) : "l"(p));
    return a;
}
__device__ __forceinline__ void ldmatrix_x4(uint32_t* r, uint32_t addr) {
    asm volatile("ldmatrix.sync.aligned.m8n8.x4.shared.b16 {%0,%1,%2,%3}, [%4];"
        : "=r"(r[0]), "=r"(r[1]), "=r"(r[2]), "=r"(r[3]) : "r"(addr));
}
__device__ __forceinline__ void ldmatrix_x2(uint32_t* r, uint32_t addr) {
    asm volatile("ldmatrix.sync.aligned.m8n8.x2.shared.b16 {%0,%1}, [%2];"
        : "=r"(r[0]), "=r"(r[1]) : "r"(addr));
}
__device__ __forceinline__ void ldmatrix_x2_trans(uint32_t* r, uint32_t addr) {
    asm volatile("ldmatrix.sync.aligned.m8n8.x2.trans.shared.b16 {%0,%1}, [%2];"
        : "=r"(r[0]), "=r"(r[1]) : "r"(addr));
}
__device__ __forceinline__ void mma16816(float* c, const uint32_t* a, const uint32_t* b) {
    asm volatile("mma.sync.aligned.m16n8k16.row.col.f32.bf16.bf16.f32 "
        "{%0,%1,%2,%3}, {%4,%5,%6,%7}, {%8,%9}, {%0,%1,%2,%3};"
        : "+f"(c[0]), "+f"(c[1]), "+f"(c[2]), "+f"(c[3])
        : "r"(a[0]), "r"(a[1]), "r"(a[2]), "r"(a[3]), "r"(b[0]), "r"(b[1]));
}
#define CP_ASYNC16(saddr, gptr) \
    asm volatile("cp.async.cg.shared.global [%0], [%1], 16;" \
        :: "r"(saddr), "l"(gptr) : "memory")
#define CP_COMMIT() asm volatile("cp.async.commit_group;" ::: "memory")
#define CP_WAIT(N)  asm volatile("cp.async.wait_group %0;" :: "n"(N) : "memory")

// split a float into bf16 hi/lo, pack two (lo index = even col)
__device__ __forceinline__ void split2(float v0, float v1, uint32_t& h, uint32_t& l) {
    __nv_bfloat16 h0 = __float2bfloat16(v0), h1 = __float2bfloat16(v1);
    __nv_bfloat162 hp; hp.x = h0; hp.y = h1;
    h = *(uint32_t*)&hp;
    __nv_bfloat16 l0 = __float2bfloat16(v0 - __bfloat162float(h0));
    __nv_bfloat16 l1 = __float2bfloat16(v1 - __bfloat162float(h1));
    __nv_bfloat162 lp; lp.x = l0; lp.y = l1;
    l = *(uint32_t*)&lp;
}

// ============================================================
// Conversion kernels
// ============================================================
__global__ void xconv_kernel(const float* __restrict__ x,
                             __nv_bfloat16* __restrict__ xh,
                             __nv_bfloat16* __restrict__ xl)
{
    int i = blockIdx.x * blockDim.x + threadIdx.x;
    if (i >= NTOK*DMODEL) return;
    float v = x[i];
    __nv_bfloat16 h = __float2bfloat16(v);
    xh[i] = h;
    xl[i] = __float2bfloat16(v - __bfloat162float(h));
}

__global__ void wconv_kernel(const float* __restrict__ W0, const float* __restrict__ W1,
                             const float* __restrict__ W2, const float* __restrict__ W3,
                             __nv_bfloat16* __restrict__ th, __nv_bfloat16* __restrict__ tl)
{
    __shared__ float s[32][33];
    const float* W = (blockIdx.z == 0) ? W0 : (blockIdx.z == 1) ? W1
                   : (blockIdx.z == 2) ? W2 : W3;
    size_t zoff = (size_t)blockIdx.z * DMODEL * DMODEL;
    int n0 = blockIdx.x * 32, k0 = blockIdx.y * 32;
    int tx = threadIdx.x, ty = threadIdx.y;   // 32 x 8
    #pragma unroll
    for (int j = 0; j < 4; j++)
        s[ty + j*8][tx] = W[(size_t)(k0 + ty + j*8)*DMODEL + n0 + tx];
    __syncthreads();
    #pragma unroll
    for (int j = 0; j < 4; j++) {
        float v = s[tx][ty + j*8];
        __nv_bfloat16 h = __float2bfloat16(v);
        size_t o = zoff + (size_t)(n0 + ty + j*8)*DMODEL + k0 + tx;
        th[o] = h;
        tl[o] = __float2bfloat16(v - __bfloat162float(h));
    }
}

// ============================================================
// mma.sync bf16x3 GEMM, 128x128 CTA tile, 8 warps (2m x 4n),
// warp = 64x32 via 4x4 m16n8k16; variant-outer MMA order.
// MODE 0: plain f32 out.  MODE 1: fused QKV (z: 0=q,1=k scatter f32; 2=v bf16 hl).
// ============================================================
#define KC 32
#define ROW_STRIDE 40
#define MAT_BYTES (128*ROW_STRIDE*2)       // 10240
#define BUF_BYTES (4*MAT_BYTES)            // 40960
#define GEMM_SMEM (2*BUF_BYTES)            // 81920

template<int MODE>
__global__ __launch_bounds__(256, 1)
void mma_gemm(const __nv_bfloat16* __restrict__ Ah, const __nv_bfloat16* __restrict__ Al,
              const __nv_bfloat16* __restrict__ Bh0, const __nv_bfloat16* __restrict__ Bl0,
              float* __restrict__ C0, float* __restrict__ C1,
              __nv_bfloat16* __restrict__ Cvh, __nv_bfloat16* __restrict__ Cvl)
{
    extern __shared__ char smem[];
    uint32_t sbase = smem_u32(smem);
    int tid = threadIdx.x, wid = tid >> 5, lane = tid & 31;
    int n0 = blockIdx.x * 128, m0 = blockIdx.y * 128;
    int z = (MODE == 1) ? blockIdx.z : 0;

    const __nv_bfloat16* Bh = Bh0 + (size_t)z * DMODEL * DMODEL;
    const __nv_bfloat16* Bl = Bl0 + (size_t)z * DMODEL * DMODEL;

    int mat = tid >> 6;
    int tp  = tid & 63;
    const __nv_bfloat16* gsrc =
        (mat == 0) ? Ah + (size_t)m0*DMODEL :
        (mat == 1) ? Al + (size_t)m0*DMODEL :
        (mat == 2) ? Bh + (size_t)n0*DMODEL :
                     Bl + (size_t)n0*DMODEL;
    uint32_t s_mat = sbase + mat*MAT_BYTES;

    int warp_m = wid & 1, warp_n = wid >> 1;

    float acc[4][4][4];
    #pragma unroll
    for (int a = 0; a < 4; a++)
        #pragma unroll
        for (int b = 0; b < 4; b++)
            #pragma unroll
            for (int c = 0; c < 4; c++) acc[a][b][c] = 0.f;

    {
        const __nv_bfloat16* g = gsrc;
        #pragma unroll
        for (int it = 0; it < 8; it++) {
            int idx = tp + it*64;
            int row = idx >> 2, c4 = idx & 3;
            CP_ASYNC16(s_mat + row*(ROW_STRIDE*2) + c4*16,
                       g + (size_t)row*DMODEL + c4*8);
        }
        CP_COMMIT();
    }

    for (int c = 0; c < DMODEL/KC; c++) {
        int buf = c & 1;
        if (c + 1 < DMODEL/KC) {
            const __nv_bfloat16* g = gsrc + (c + 1)*KC;
            uint32_t sb2 = s_mat + (buf ^ 1)*BUF_BYTES;
            #pragma unroll
            for (int it = 0; it < 8; it++) {
                int idx = tp + it*64;
                int row = idx >> 2, c4 = idx & 3;
                CP_ASYNC16(sb2 + row*(ROW_STRIDE*2) + c4*16,
                           g + (size_t)row*DMODEL + c4*8);
            }
            CP_COMMIT();
            CP_WAIT(1);
        } else {
            CP_WAIT(0);
        }
        __syncthreads();

        uint32_t b_off = sbase + buf*BUF_BYTES;
        #pragma unroll
        for (int ks = 0; ks < 2; ks++) {
            int k0 = ks * 16;
            uint32_t a_h[4][4], a_l[4][4], b_h[4][2], b_l[4][2];
            #pragma unroll
            for (int mt = 0; mt < 4; mt++) {
                int row = warp_m*64 + mt*16 + (lane & 15);
                uint32_t col = k0 + ((lane >> 4) << 3);
                uint32_t off = b_off + (row*ROW_STRIDE + col)*2;
                ldmatrix_x4(a_h[mt], off);
                ldmatrix_x4(a_l[mt], off + MAT_BYTES);
            }
            #pragma unroll
            for (int nt = 0; nt < 4; nt++) {
                int row = warp_n*32 + nt*8 + (lane & 7);
                uint32_t col = k0 + (((lane >> 3) & 1) << 3);
                uint32_t off = b_off + (row*ROW_STRIDE + col)*2;
                ldmatrix_x2(b_h[nt], off + 2*MAT_BYTES);
                ldmatrix_x2(b_l[nt], off + 3*MAT_BYTES);
            }
            // variant-outer: same-acc reuse distance 16
            #pragma unroll
            for (int mt = 0; mt < 4; mt++)
                #pragma unroll
                for (int nt = 0; nt < 4; nt++)
                    mma16816(acc[mt][nt], a_h[mt], b_h[nt]);
            #pragma unroll
            for (int mt = 0; mt < 4; mt++)
                #pragma unroll
                for (int nt = 0; nt < 4; nt++)
                    mma16816(acc[mt][nt], a_h[mt], b_l[nt]);
            #pragma unroll
            for (int mt = 0; mt < 4; mt++)
                #pragma unroll
                for (int nt = 0; nt < 4; nt++)
                    mma16816(acc[mt][nt], a_l[mt], b_h[nt]);
        }
        __syncthreads();
    }

    // epilogue
    int qrow = lane >> 2, qcol = (lane & 3) * 2;
    #pragma unroll
    for (int mt = 0; mt < 4; mt++) {
        #pragma unroll
        for (int nt = 0; nt < 4; nt++) {
            int row0 = m0 + warp_m*64 + mt*16 + qrow;
            int col  = n0 + warp_n*32 + nt*8 + qcol;
            float2 v0 = make_float2(acc[mt][nt][0], acc[mt][nt][1]);
            float2 v1 = make_float2(acc[mt][nt][2], acc[mt][nt][3]);
            if (MODE == 0) {
                *(float2*)&C0[(size_t)row0*DMODEL + col] = v0;
                *(float2*)&C0[(size_t)(row0 + 8)*DMODEL + col] = v1;
            } else if (z < 2) {
                float* C = z ? C1 : C0;
                int h = col >> 6, d = col & 63;
                int b0 = row0 >> 10, t0 = row0 & 1023;
                *(float2*)&C[((size_t)((b0*NHEADS + h)*SEQ + t0))*DHEAD + d] = v0;
                int r1 = row0 + 8;
                int b1 = r1 >> 10, t1 = r1 & 1023;
                *(float2*)&C[((size_t)((b1*NHEADS + h)*SEQ + t1))*DHEAD + d] = v1;
            } else {
                int h = col >> 6, d = col & 63;
                #pragma unroll
                for (int rr = 0; rr < 2; rr++) {
                    int row = row0 + rr*8;
                    float2 v = rr ? v1 : v0;
                    int b = row >> 10, t = row & 1023;
                    size_t o = ((size_t)((b*NHEADS + h)*SEQ + t))*DHEAD + d;
                    __nv_bfloat16 h0 = __float2bfloat16(v.x), h1 = __float2bfloat16(v.y);
                    __nv_bfloat162 hp; hp.x = h0; hp.y = h1;
                    *(__nv_bfloat162*)&Cvh[o] = hp;
                    __nv_bfloat162 lp;
                    lp.x = __float2bfloat16(v.x - __bfloat162float(h0));
                    lp.y = __float2bfloat16(v.y - __bfloat162float(h1));
                    *(__nv_bfloat162*)&Cvl[o] = lp;
                }
            }
        }
    }
}

// ============================================================
// RoPE in-place on q and k  (layout [bh][t][64])
// ============================================================
__global__ void rope_kernel(float* __restrict__ q, float* __restrict__ k)
{
    int idx = blockIdx.x * blockDim.x + threadIdx.x;
    if (idx >= NBHT*32) return;
    int i = idx & 31;
    int n = idx >> 5;
    int t = n & 1023;
    float inv = (float)(1.0 / pow(10000.0, (double)i / 32.0));
    float ang = (float)t * inv;
    float s, c;
    sincosf(ang, &s, &c);
    size_t base = (size_t)n * DHEAD;
    float q1 = q[base+i], q2 = q[base+i+32];
    q[base+i]    = q1*c - q2*s;
    q[base+i+32] = q1*s + q2*c;
    float k1 = k[base+i], k2 = k[base+i+32];
    k[base+i]    = k1*c - k2*s;
    k[base+i+32] = k1*s + k2*c;
}

// ============================================================
// Feature kernel -> bf16 hi/lo u and w rows [n][80]
// ============================================================
__global__ void feature_kernel(const float* __restrict__ q, const float* __restrict__ k,
                               const float* __restrict__ Wqm, const float* __restrict__ Wkm,
                               const float* __restrict__ Wm,
                               __nv_bfloat16* __restrict__ uhg, __nv_bfloat16* __restrict__ ulg,
                               __nv_bfloat16* __restrict__ whg, __nv_bfloat16* __restrict__ wlg)
{
    __shared__ float sWqm[512], sWkm[512], sWm[512];
    __shared__ float sOut[64][81];

    int tid = threadIdx.x;           // 64 threads
    int n0 = blockIdx.x * 64;
    int n  = n0 + tid;

    for (int p = tid; p < 512; p += 64) {
        sWqm[p] = Wqm[p]; sWkm[p] = Wkm[p]; sWm[p] = Wm[p];
    }
    __syncthreads();

    // projections: direct row reads (float4)
    const float4* qr = (const float4*)(q + (size_t)n*64);
    const float4* kr = (const float4*)(k + (size_t)n*64);
    float qm[8], km[8];
    #pragma unroll
    for (int m = 0; m < 8; m++) { qm[m] = 0.f; km[m] = 0.f; }
    #pragma unroll
    for (int d4 = 0; d4 < 16; d4++) {
        float4 qv = qr[d4], kv = kr[d4];
        const float* qf = (const float*)&qv;
        const float* kf = (const float*)&kv;
        #pragma unroll
        for (int j = 0; j < 4; j++) {
            int d = d4*4 + j;
            #pragma unroll
            for (int m = 0; m < 8; m++) {
                qm[m] = fmaf(qf[j], sWqm[d*8+m], qm[m]);
                km[m] = fmaf(kf[j], sWkm[d*8+m], km[m]);
            }
        }
    }
    #pragma unroll
    for (int m = 0; m < 8; m++) {
        qm[m] = 1.0f / (1.0f + expf(-qm[m]));
        km[m] = 1.0f / (1.0f + expf(-km[m]));
    }

    float A[64];
    #pragma unroll
    for (int nn = 0; nn < 64; nn++) {
        float s = 0.f;
        #pragma unroll
        for (int m = 0; m < 8; m++) s = fmaf(qm[m], sWm[m*64+nn], s);
        A[nn] = s;
    }

    // stage u into sOut
    float Gq[8];
    #pragma unroll
    for (int d = 0; d < 8; d++) Gq[d] = 0.f;
    #pragma unroll
    for (int d = 0; d < 8; d++) {
        #pragma unroll
        for (int f = 0; f < 8; f++) {
            float g = 0.f;
            #pragma unroll
            for (int e = 0; e < 8; e++) g = fmaf(A[d*8+e], A[f*8+e], g);
            if (d == f) g += EPS_PSD;
            Gq[d] = fmaf(g, qm[f], Gq[d]);
            sOut[tid][8 + d*8 + f] = -g;
        }
    }
    float qGq = 0.f;
    #pragma unroll
    for (int d = 0; d < 8; d++) {
        qGq = fmaf(Gq[d], qm[d], qGq);
        sOut[tid][d] = 2.0f * Gq[d];
    }
    sOut[tid][72] = -qGq;
    #pragma unroll
    for (int p = 73; p < 80; p++) sOut[tid][p] = 0.f;
    __syncthreads();

    // coalesced flush of u
    for (int p = tid; p < 64*80; p += 64) {
        int r = p / 80, c = p % 80;
        float v = sOut[r][c];
        __nv_bfloat16 h = __float2bfloat16(v);
        size_t o = (size_t)(n0 + r)*UDIM + c;
        uhg[o] = h;
        ulg[o] = __float2bfloat16(v - __bfloat162float(h));
    }
    __syncthreads();

    // stage w
    #pragma unroll
    for (int d = 0; d < 8; d++) sOut[tid][d] = km[d];
    #pragma unroll
    for (int d = 0; d < 8; d++)
        #pragma unroll
        for (int f = 0; f < 8; f++)
            sOut[tid][8 + d*8 + f] = km[d]*km[f];
    sOut[tid][72] = 1.0f;
    #pragma unroll
    for (int p = 73; p < 80; p++) sOut[tid][p] = 0.f;
    __syncthreads();

    for (int p = tid; p < 64*80; p += 64) {
        int r = p / 80, c = p % 80;
        float v = sOut[r][c];
        __nv_bfloat16 h = __float2bfloat16(v);
        size_t o = (size_t)(n0 + r)*UDIM + c;
        whg[o] = h;
        wlg[o] = __float2bfloat16(v - __bfloat162float(h));
    }
}

// ============================================================
// Tensor-core flash: S = U.W^T (bf16x3), P = exp(min(S,0)/temp) (no max
// tracking: S<=0 always), O = P.V (bf16x3), split-k over warp_n.
// 64x64 tiles, 8 warps (warp_m 2 x warp_n 4).
// ============================================================
#define FL_USTR 88
#define FL_VSTR 72
#define FL_OFF_UL (64*FL_USTR*2)            // 11264
#define FL_OFF_W  (2*64*FL_USTR*2)          // 22528
#define FL_WBUF   (2*64*FL_USTR*2)          // 22528
#define FL_OFF_V  (FL_OFF_W + 2*FL_WBUF)    // 67584
#define FL_VBUF   (2*64*FL_VSTR*2)          // 18432
#define FLASH_SMEM (FL_OFF_V + 2*FL_VBUF)   // 104448

__global__ __launch_bounds__(256, 1)
void flash_mma(const __nv_bfloat16* __restrict__ uh, const __nv_bfloat16* __restrict__ ul,
               const __nv_bfloat16* __restrict__ wh, const __nv_bfloat16* __restrict__ wl,
               const __nv_bfloat16* __restrict__ vh, const __nv_bfloat16* __restrict__ vl,
               __nv_bfloat16* __restrict__ oh, __nv_bfloat16* __restrict__ ol,
               const float* __restrict__ temperature)
{
    extern __shared__ char smem[];
    uint32_t sb = smem_u32(smem);
    int tid = threadIdx.x, wid = tid >> 5, lane = tid & 31;
    int warp_m = wid & 1, warp_n = wid >> 1;
    int bh = blockIdx.y;
    int ib = (int)(gridDim.x - 1 - blockIdx.x);
    float inv_temp = 1.f / fmaxf(temperature[0], 0.1f);

    // U tile load
    {
        const char* gh = (const char*)(uh + (size_t)(bh*SEQ + ib*64)*UDIM);
        const char* gl = (const char*)(ul + (size_t)(bh*SEQ + ib*64)*UDIM);
        for (int p = tid; p < 640; p += 256) {
            int r = p / 10, c = p % 10;
            CP_ASYNC16(sb + r*(FL_USTR*2) + c*16, gh + r*160 + c*16);
            CP_ASYNC16(sb + FL_OFF_UL + r*(FL_USTR*2) + c*16, gl + r*160 + c*16);
        }
    }
    // W/V tile loader
    #define ISSUE_WV(jb, buf) do { \
        const char* gwh = (const char*)(wh + (size_t)(bh*SEQ + (jb)*64)*UDIM); \
        const char* gwl = (const char*)(wl + (size_t)(bh*SEQ + (jb)*64)*UDIM); \
        uint32_t wdst = sb + FL_OFF_W + (buf)*FL_WBUF; \
        for (int p = tid; p < 640; p += 256) { \
            int r = p / 10, c = p % 10; \
            CP_ASYNC16(wdst + r*176 + c*16, gwh + r*160 + c*16); \
            CP_ASYNC16(wdst + 11264 + r*176 + c*16, gwl + r*160 + c*16); \
        } \
        const char* gvh = (const char*)(vh + (size_t)(bh*SEQ + (jb)*64)*DHEAD); \
        const char* gvl = (const char*)(vl + (size_t)(bh*SEQ + (jb)*64)*DHEAD); \
        uint32_t vdst = sb + FL_OFF_V + (buf)*FL_VBUF; \
        for (int p = tid; p < 512; p += 256) { \
            int r = p / 8, c = p % 8; \
            CP_ASYNC16(vdst + r*144 + c*16, gvh + r*128 + c*16); \
            CP_ASYNC16(vdst + 9216 + r*144 + c*16, gvl + r*128 + c*16); \
        } \
    } while (0)

    ISSUE_WV(0, 0);
    CP_COMMIT();

    float accO[2][8][4];
    float l_acc[4];
    #pragma unroll
    for (int i = 0; i < 4; i++) l_acc[i] = 0.f;
    #pragma unroll
    for (int mt = 0; mt < 2; mt++)
        #pragma unroll
        for (int nt = 0; nt < 8; nt++)
            #pragma unroll
            for (int r = 0; r < 4; r++) accO[mt][nt][r] = 0.f;

    for (int jb = 0; jb <= ib; jb++) {
        int buf = jb & 1;
        if (jb < ib) { ISSUE_WV(jb+1, buf^1); CP_COMMIT(); CP_WAIT(1); }
        else CP_WAIT(0);
        __syncthreads();

        uint32_t sw_h = sb + FL_OFF_W + buf*FL_WBUF;
        uint32_t sw_l = sw_h + 11264;
        uint32_t sv_h = sb + FL_OFF_V + buf*FL_VBUF;
        uint32_t sv_l = sv_h + 9216;

        // ---- S = U . W^T ----
        float sc[2][2][4];
        #pragma unroll
        for (int mt = 0; mt < 2; mt++)
            #pragma unroll
            for (int nt = 0; nt < 2; nt++)
                #pragma unroll
                for (int r = 0; r < 4; r++) sc[mt][nt][r] = 0.f;

        #pragma unroll
        for (int k5 = 0; k5 < 5; k5++) {
            int k0 = k5*16;
            uint32_t a_h[2][4], a_l[2][4], b_h[2][2], b_l[2][2];
            #pragma unroll
            for (int mt = 0; mt < 2; mt++) {
                int row = warp_m*32 + mt*16 + (lane & 15);
                uint32_t off = (uint32_t)(row*FL_USTR + k0 + ((lane >> 4) << 3))*2;
                ldmatrix_x4(a_h[mt], sb + off);
                ldmatrix_x4(a_l[mt], sb + FL_OFF_UL + off);
            }
            #pragma unroll
            for (int nt = 0; nt < 2; nt++) {
                int row = warp_n*16 + nt*8 + (lane & 7);
                uint32_t off = (uint32_t)(row*FL_USTR + k0 + (((lane >> 3) & 1) << 3))*2;
                ldmatrix_x2(b_h[nt], sw_h + off);
                ldmatrix_x2(b_l[nt], sw_l + off);
            }
            #pragma unroll
            for (int mt = 0; mt < 2; mt++)
                #pragma unroll
                for (int nt = 0; nt < 2; nt++)
                    mma16816(sc[mt][nt], a_h[mt], b_h[nt]);
            #pragma unroll
            for (int mt = 0; mt < 2; mt++)
                #pragma unroll
                for (int nt = 0; nt < 2; nt++)
                    mma16816(sc[mt][nt], a_h[mt], b_l[nt]);
            #pragma unroll
            for (int mt = 0; mt < 2; mt++)
                #pragma unroll
                for (int nt = 0; nt < 2; nt++)
                    mma16816(sc[mt][nt], a_l[mt], b_h[nt]);
        }

        // ---- P = exp(min(S,0)/temp), causal mask, row-sum partials ----
        bool diag = (jb == ib);
        uint32_t ph[2][4], pl[2][4];
        #pragma unroll
        for (int mt = 0; mt < 2; mt++) {
            #pragma unroll
            for (int half = 0; half < 2; half++) {
                int t_g = ib*64 + warp_m*32 + mt*16 + (lane >> 2) + half*8;
                float pv[4];
                #pragma unroll
                for (int nt = 0; nt < 2; nt++) {
                    #pragma unroll
                    for (int cc = 0; cc < 2; cc++) {
                        int s_g = jb*64 + warp_n*16 + nt*8 + (lane & 3)*2 + cc;
                        float v = sc[mt][nt][half*2 + cc];
                        float p = __expf(fminf(v, 0.f) * inv_temp);
                        if (diag && s_g > t_g) p = 0.f;
                        pv[nt*2 + cc] = p;
                    }
                }
                float ls = pv[0] + pv[1] + pv[2] + pv[3];
                ls += __shfl_xor_sync(0xffffffffu, ls, 1);
                ls += __shfl_xor_sync(0xffffffffu, ls, 2);
                l_acc[mt*2 + half] += ls;
                split2(pv[0], pv[1], ph[mt][half], pl[mt][half]);
                split2(pv[2], pv[3], ph[mt][2 + half], pl[mt][2 + half]);
            }
        }

        // ---- O += P . V  (k-slice = warp_n's 16 s) ----
        #pragma unroll
        for (int ntp = 0; ntp < 4; ntp++) {
            uint32_t v_h[2][2], v_l[2][2];
            #pragma unroll
            for (int q2 = 0; q2 < 2; q2++) {
                int nt = ntp*2 + q2;
                uint32_t off = (uint32_t)((warp_n*16 + (lane & 15))*FL_VSTR + nt*8)*2;
                ldmatrix_x2_trans(v_h[q2], sv_h + off);
                ldmatrix_x2_trans(v_l[q2], sv_l + off);
            }
            #pragma unroll
            for (int mt = 0; mt < 2; mt++)
                #pragma unroll
                for (int q2 = 0; q2 < 2; q2++)
                    mma16816(accO[mt][ntp*2+q2], ph[mt], v_h[q2]);
            #pragma unroll
            for (int mt = 0; mt < 2; mt++)
                #pragma unroll
                for (int q2 = 0; q2 < 2; q2++)
                    mma16816(accO[mt][ntp*2+q2], ph[mt], v_l[q2]);
            #pragma unroll
            for (int mt = 0; mt < 2; mt++)
                #pragma unroll
                for (int q2 = 0; q2 < 2; q2++)
                    mma16816(accO[mt][ntp*2+q2], pl[mt], v_h[q2]);
        }
        __syncthreads();   // all warps done with this buffer before it is refilled
    }

    // ---- cross-warp_n reduction (staged) ----
    float* sO   = (float*)smem;                 // [64][66]
    float* lred = (float*)(smem + 64*66*4);     // [64]
    #pragma unroll 1
    for (int stage = 0; stage < 4; stage++) {
        if (warp_n == stage) {
            #pragma unroll
            for (int mt = 0; mt < 2; mt++) {
                #pragma unroll
                for (int half = 0; half < 2; half++) {
                    int r = warp_m*32 + mt*16 + (lane >> 2) + half*8;
                    #pragma unroll
                    for (int nt = 0; nt < 8; nt++) {
                        int cc = nt*8 + (lane & 3)*2;
                        float v0 = accO[mt][nt][half*2 + 0];
                        float v1 = accO[mt][nt][half*2 + 1];
                        if (stage == 0) { sO[r*66+cc] = v0; sO[r*66+cc+1] = v1; }
                        else            { sO[r*66+cc] += v0; sO[r*66+cc+1] += v1; }
                    }
                    if ((lane & 3) == 0) {
                        if (stage == 0) lred[r] = l_acc[mt*2 + half];
                        else            lred[r] += l_acc[mt*2 + half];
                    }
                }
            }
        }
        __syncthreads();
    }

    // ---- normalize + write bf16 hi/lo token-major ----
    int b = bh >> 4, h = bh & 15;
    for (int p = tid; p < 4096; p += 256) {
        int t = p >> 6, d = p & 63;
        float v = sO[t*66 + d] / lred[t];
        __nv_bfloat16 hv = __float2bfloat16(v);
        size_t o = ((size_t)(b*SEQ + ib*64 + t))*DMODEL + h*64 + d;
        oh[o] = hv;
        ol[o] = __float2bfloat16(v - __bfloat162float(hv));
    }
}

// ============================================================
extern "C" void kernel_launch(void* const* d_in, const int* in_sizes, int n_in,
                              void* d_out, int out_size)
{
    (void)in_sizes; (void)n_in; (void)out_size;
    const float* x    = (const float*)d_in[0];
    const float* Wq   = (const float*)d_in[1];
    const float* Wk   = (const float*)d_in[2];
    const float* Wv   = (const float*)d_in[3];
    const float* Wo   = (const float*)d_in[4];
    const float* Wqm  = (const float*)d_in[5];
    const float* Wkm  = (const float*)d_in[6];
    const float* Wm   = (const float*)d_in[7];
    const float* temp = (const float*)d_in[8];

    float *q, *k;
    __nv_bfloat16 *xh, *xl, *wth, *wtl, *vh, *vl, *uh, *ul, *wwh, *wwl, *a2h, *a2l;
    cudaGetSymbolAddress((void**)&q,   g_q);
    cudaGetSymbolAddress((void**)&k,   g_k);
    cudaGetSymbolAddress((void**)&xh,  g_xh);
    cudaGetSymbolAddress((void**)&xl,  g_xl);
    cudaGetSymbolAddress((void**)&wth, g_wth);
    cudaGetSymbolAddress((void**)&wtl, g_wtl);
    cudaGetSymbolAddress((void**)&vh,  g_vh);
    cudaGetSymbolAddress((void**)&vl,  g_vl);
    cudaGetSymbolAddress((void**)&uh,  g_uh);
    cudaGetSymbolAddress((void**)&ul,  g_ul);
    cudaGetSymbolAddress((void**)&wwh, g_wh);
    cudaGetSymbolAddress((void**)&wwl, g_wl);
    cudaGetSymbolAddress((void**)&a2h, g_a2h);
    cudaGetSymbolAddress((void**)&a2l, g_a2l);

    cudaFuncSetAttribute(mma_gemm<0>, cudaFuncAttributeMaxDynamicSharedMemorySize, GEMM_SMEM);
    cudaFuncSetAttribute(mma_gemm<1>, cudaFuncAttributeMaxDynamicSharedMemorySize, GEMM_SMEM);
    cudaFuncSetAttribute(flash_mma,  cudaFuncAttributeMaxDynamicSharedMemorySize, FLASH_SMEM);

    wconv_kernel<<<dim3(32, 32, 4), dim3(32, 8)>>>(Wq, Wk, Wv, Wo, wth, wtl);
    xconv_kernel<<<(NTOK*DMODEL)/256, 256>>>(x, xh, xl);

    // fused QKV (z=0 q, z=1 k f32 scatter; z=2 v bf16 hi/lo)
    size_t WSZ = (size_t)DMODEL*DMODEL;
    mma_gemm<1><<<dim3(DMODEL/128, NTOK/128, 3), 256, GEMM_SMEM>>>(
        xh, xl, wth, wtl, q, k, vh, vl);

    rope_kernel<<<(NBHT*32)/256, 256>>>(q, k);

    feature_kernel<<<NBHT/64, 64>>>(q, k, Wqm, Wkm, Wm, uh, ul, wwh, wwl);

    flash_mma<<<dim3(SEQ/64, BATCH*NHEADS), 256, FLASH_SMEM>>>(
        uh, ul, wwh, wwl, vh, vl, a2h, a2l, temp);

    mma_gemm<0><<<dim3(DMODEL/128, NTOK/128, 1), 256, GEMM_SMEM>>>(
        a2h, a2l, wth + 3*WSZ, wtl + 3*WSZ, (float*)d_out,
        nullptr, nullptr, nullptr);
}

// round 5
// speedup vs baseline: 2.4582x; 1.0118x over previous
#include <cuda_runtime.h>
#include <cuda_bf16.h>
#include <math.h>
#include <stdint.h>

// Problem constants
#define BATCH   2
#define SEQ     1024
#define DMODEL  1024
#define NHEADS  16
#define DHEAD   64
#define NTOK    (BATCH*SEQ)          // 2048
#define NBHT    (BATCH*NHEADS*SEQ)   // 32768
#define UDIM    80                   // 73 padded to 80
#define EPS_PSD 0.001f

// -------- device scratch (static, no allocations) --------
__device__ float g_q[NBHT*DHEAD];
__device__ float g_k[NBHT*DHEAD];
__device__ float g_cos[SEQ*32];
__device__ float g_sin[SEQ*32];

__device__ __nv_bfloat16 g_xh[NTOK*DMODEL];
__device__ __nv_bfloat16 g_xl[NTOK*DMODEL];
__device__ __nv_bfloat16 g_wth[4*DMODEL*DMODEL]; // Wq,Wk,Wv,Wo transposed [n][k]
__device__ __nv_bfloat16 g_wtl[4*DMODEL*DMODEL];

__device__ __nv_bfloat16 g_vh[NBHT*DHEAD];       // V bf16 hi/lo [bh][t][d]
__device__ __nv_bfloat16 g_vl[NBHT*DHEAD];

__device__ __nv_bfloat16 g_uh[NBHT*UDIM];        // u rows bf16 hi/lo [n][80]
__device__ __nv_bfloat16 g_ul[NBHT*UDIM];
__device__ __nv_bfloat16 g_wh[NBHT*UDIM];        // w rows bf16 hi/lo [n][80]
__device__ __nv_bfloat16 g_wl[NBHT*UDIM];

__device__ __nv_bfloat16 g_a2h[NTOK*DMODEL];     // attention out, token-major
__device__ __nv_bfloat16 g_a2l[NTOK*DMODEL];

// ============================================================
// PTX helpers
// ============================================================
__device__ __forceinline__ uint32_t smem_u32(const void* p) {
    uint32_t a;
    asm("{ .reg .u64 t; cvta.to.shared.u64 t, %1; cvt.u32.u64 %0, t; }" : "=r"(a) : "l"(p));
    return a;
}
__device__ __forceinline__ void ldmatrix_x4(uint32_t* r, uint32_t addr) {
    asm volatile("ldmatrix.sync.aligned.m8n8.x4.shared.b16 {%0,%1,%2,%3}, [%4];"
        : "=r"(r[0]), "=r"(r[1]), "=r"(r[2]), "=r"(r[3]) : "r"(addr));
}
__device__ __forceinline__ void ldmatrix_x2(uint32_t* r, uint32_t addr) {
    asm volatile("ldmatrix.sync.aligned.m8n8.x2.shared.b16 {%0,%1}, [%2];"
        : "=r"(r[0]), "=r"(r[1]) : "r"(addr));
}
__device__ __forceinline__ void ldmatrix_x2_trans(uint32_t* r, uint32_t addr) {
    asm volatile("ldmatrix.sync.aligned.m8n8.x2.trans.shared.b16 {%0,%1}, [%2];"
        : "=r"(r[0]), "=r"(r[1]) : "r"(addr));
}
__device__ __forceinline__ void mma16816(float* c, const uint32_t* a, const uint32_t* b) {
    asm volatile("mma.sync.aligned.m16n8k16.row.col.f32.bf16.bf16.f32 "
        "{%0,%1,%2,%3}, {%4,%5,%6,%7}, {%8,%9}, {%0,%1,%2,%3};"
        : "+f"(c[0]), "+f"(c[1]), "+f"(c[2]), "+f"(c[3])
        : "r"(a[0]), "r"(a[1]), "r"(a[2]), "r"(a[3]), "r"(b[0]), "r"(b[1]));
}
#define CP_ASYNC16(saddr, gptr) \
    asm volatile("cp.async.cg.shared.global [%0], [%1], 16;" \
        :: "r"(saddr), "l"(gptr) : "memory")
#define CP_COMMIT() asm volatile("cp.async.commit_group;" ::: "memory")
#define CP_WAIT(N)  asm volatile("cp.async.wait_group %0;" :: "n"(N) : "memory")

__device__ __forceinline__ void split2(float v0, float v1, uint32_t& h, uint32_t& l) {
    __nv_bfloat16 h0 = __float2bfloat16(v0), h1 = __float2bfloat16(v1);
    __nv_bfloat162 hp; hp.x = h0; hp.y = h1;
    h = *(uint32_t*)&hp;
    __nv_bfloat16 l0 = __float2bfloat16(v0 - __bfloat162float(h0));
    __nv_bfloat16 l1 = __float2bfloat16(v1 - __bfloat162float(h1));
    __nv_bfloat162 lp; lp.x = l0; lp.y = l1;
    l = *(uint32_t*)&lp;
}

// ============================================================
// Conversion + table kernels
// ============================================================
__global__ void xconv_kernel(const float* __restrict__ x,
                             __nv_bfloat16* __restrict__ xh,
                             __nv_bfloat16* __restrict__ xl)
{
    int i = blockIdx.x * blockDim.x + threadIdx.x;
    if (i >= NTOK*DMODEL) return;
    float v = x[i];
    __nv_bfloat16 h = __float2bfloat16(v);
    xh[i] = h;
    xl[i] = __float2bfloat16(v - __bfloat162float(h));
}

__global__ void wconv_kernel(const float* __restrict__ W0, const float* __restrict__ W1,
                             const float* __restrict__ W2, const float* __restrict__ W3,
                             __nv_bfloat16* __restrict__ th, __nv_bfloat16* __restrict__ tl)
{
    __shared__ float s[32][33];
    const float* W = (blockIdx.z == 0) ? W0 : (blockIdx.z == 1) ? W1
                   : (blockIdx.z == 2) ? W2 : W3;
    size_t zoff = (size_t)blockIdx.z * DMODEL * DMODEL;
    int n0 = blockIdx.x * 32, k0 = blockIdx.y * 32;
    int tx = threadIdx.x, ty = threadIdx.y;   // 32 x 8
    #pragma unroll
    for (int j = 0; j < 4; j++)
        s[ty + j*8][tx] = W[(size_t)(k0 + ty + j*8)*DMODEL + n0 + tx];
    __syncthreads();
    #pragma unroll
    for (int j = 0; j < 4; j++) {
        float v = s[tx][ty + j*8];
        __nv_bfloat16 h = __float2bfloat16(v);
        size_t o = zoff + (size_t)(n0 + ty + j*8)*DMODEL + k0 + tx;
        th[o] = h;
        tl[o] = __float2bfloat16(v - __bfloat162float(h));
    }
}

__global__ void rope_table_kernel(float* __restrict__ ct, float* __restrict__ st)
{
    int idx = blockIdx.x * blockDim.x + threadIdx.x;
    if (idx >= SEQ*32) return;
    int i = idx & 31, t = idx >> 5;
    float inv = (float)(1.0 / pow(10000.0, (double)i / 32.0));
    float ang = (float)t * inv;
    float s, c;
    sincosf(ang, &s, &c);
    ct[idx] = c;
    st[idx] = s;
}

// ============================================================
// mma.sync bf16x3 GEMM, 128x128 CTA tile, 8 warps (2m x 4n),
// warp = 64x32 via 4x4 m16n8k16; variant-outer order; 3-stage
// cp.async pipeline, single __syncthreads per K-chunk.
// MODE 0: plain f32 out.  MODE 1: fused QKV (z: 0=q,1=k f32 scatter; 2=v bf16 hl).
// ============================================================
#define KC 32
#define ROW_STRIDE 40
#define MAT_BYTES (128*ROW_STRIDE*2)       // 10240
#define BUF_BYTES (4*MAT_BYTES)            // 40960
#define GEMM_SMEM (3*BUF_BYTES)            // 122880

template<int MODE>
__global__ __launch_bounds__(256, 1)
void mma_gemm(const __nv_bfloat16* __restrict__ Ah, const __nv_bfloat16* __restrict__ Al,
              const __nv_bfloat16* __restrict__ Bh0, const __nv_bfloat16* __restrict__ Bl0,
              float* __restrict__ C0, float* __restrict__ C1,
              __nv_bfloat16* __restrict__ Cvh, __nv_bfloat16* __restrict__ Cvl)
{
    extern __shared__ char smem[];
    uint32_t sbase = smem_u32(smem);
    int tid = threadIdx.x, wid = tid >> 5, lane = tid & 31;
    int n0 = blockIdx.x * 128, m0 = blockIdx.y * 128;
    int z = (MODE == 1) ? blockIdx.z : 0;

    const __nv_bfloat16* Bh = Bh0 + (size_t)z * DMODEL * DMODEL;
    const __nv_bfloat16* Bl = Bl0 + (size_t)z * DMODEL * DMODEL;

    int mat = tid >> 6;
    int tp  = tid & 63;
    const __nv_bfloat16* gsrc =
        (mat == 0) ? Ah + (size_t)m0*DMODEL :
        (mat == 1) ? Al + (size_t)m0*DMODEL :
        (mat == 2) ? Bh + (size_t)n0*DMODEL :
                     Bl + (size_t)n0*DMODEL;

    int warp_m = wid & 1, warp_n = wid >> 1;

    float acc[4][4][4];
    #pragma unroll
    for (int a = 0; a < 4; a++)
        #pragma unroll
        for (int b = 0; b < 4; b++)
            #pragma unroll
            for (int c = 0; c < 4; c++) acc[a][b][c] = 0.f;

    #define GEMM_ISSUE(chunk, slot) do { \
        const __nv_bfloat16* g = gsrc + (chunk)*KC; \
        uint32_t sb2 = sbase + (slot)*BUF_BYTES + mat*MAT_BYTES; \
        _Pragma("unroll") \
        for (int it = 0; it < 8; it++) { \
            int idx = tp + it*64; \
            int row = idx >> 2, c4 = idx & 3; \
            CP_ASYNC16(sb2 + row*(ROW_STRIDE*2) + c4*16, \
                       g + (size_t)row*DMODEL + c4*8); \
        } \
        CP_COMMIT(); \
    } while (0)

    GEMM_ISSUE(0, 0);
    GEMM_ISSUE(1, 1);

    for (int c = 0; c < DMODEL/KC; c++) {
        int slot = c % 3;
        if (c < DMODEL/KC - 1) CP_WAIT(1); else CP_WAIT(0);
        __syncthreads();
        if (c + 2 < DMODEL/KC) GEMM_ISSUE(c + 2, (c + 2) % 3);

        uint32_t b_off = sbase + slot*BUF_BYTES;
        #pragma unroll
        for (int ks = 0; ks < 2; ks++) {
            int k0 = ks * 16;
            uint32_t a_h[4][4], a_l[4][4], b_h[4][2], b_l[4][2];
            #pragma unroll
            for (int mt = 0; mt < 4; mt++) {
                int row = warp_m*64 + mt*16 + (lane & 15);
                uint32_t col = k0 + ((lane >> 4) << 3);
                uint32_t off = b_off + (row*ROW_STRIDE + col)*2;
                ldmatrix_x4(a_h[mt], off);
                ldmatrix_x4(a_l[mt], off + MAT_BYTES);
            }
            #pragma unroll
            for (int nt = 0; nt < 4; nt++) {
                int row = warp_n*32 + nt*8 + (lane & 7);
                uint32_t col = k0 + (((lane >> 3) & 1) << 3);
                uint32_t off = b_off + (row*ROW_STRIDE + col)*2;
                ldmatrix_x2(b_h[nt], off + 2*MAT_BYTES);
                ldmatrix_x2(b_l[nt], off + 3*MAT_BYTES);
            }
            #pragma unroll
            for (int mt = 0; mt < 4; mt++)
                #pragma unroll
                for (int nt = 0; nt < 4; nt++)
                    mma16816(acc[mt][nt], a_h[mt], b_h[nt]);
            #pragma unroll
            for (int mt = 0; mt < 4; mt++)
                #pragma unroll
                for (int nt = 0; nt < 4; nt++)
                    mma16816(acc[mt][nt], a_h[mt], b_l[nt]);
            #pragma unroll
            for (int mt = 0; mt < 4; mt++)
                #pragma unroll
                for (int nt = 0; nt < 4; nt++)
                    mma16816(acc[mt][nt], a_l[mt], b_h[nt]);
        }
    }

    // epilogue
    int qrow = lane >> 2, qcol = (lane & 3) * 2;
    #pragma unroll
    for (int mt = 0; mt < 4; mt++) {
        #pragma unroll
        for (int nt = 0; nt < 4; nt++) {
            int row0 = m0 + warp_m*64 + mt*16 + qrow;
            int col  = n0 + warp_n*32 + nt*8 + qcol;
            float2 v0 = make_float2(acc[mt][nt][0], acc[mt][nt][1]);
            float2 v1 = make_float2(acc[mt][nt][2], acc[mt][nt][3]);
            if (MODE == 0) {
                *(float2*)&C0[(size_t)row0*DMODEL + col] = v0;
                *(float2*)&C0[(size_t)(row0 + 8)*DMODEL + col] = v1;
            } else if (z < 2) {
                float* C = z ? C1 : C0;
                int h = col >> 6, d = col & 63;
                int b0 = row0 >> 10, t0 = row0 & 1023;
                *(float2*)&C[((size_t)((b0*NHEADS + h)*SEQ + t0))*DHEAD + d] = v0;
                int r1 = row0 + 8;
                int b1 = r1 >> 10, t1 = r1 & 1023;
                *(float2*)&C[((size_t)((b1*NHEADS + h)*SEQ + t1))*DHEAD + d] = v1;
            } else {
                int h = col >> 6, d = col & 63;
                #pragma unroll
                for (int rr = 0; rr < 2; rr++) {
                    int row = row0 + rr*8;
                    float2 v = rr ? v1 : v0;
                    int b = row >> 10, t = row & 1023;
                    size_t o = ((size_t)((b*NHEADS + h)*SEQ + t))*DHEAD + d;
                    __nv_bfloat16 h0 = __float2bfloat16(v.x), h1 = __float2bfloat16(v.y);
                    __nv_bfloat162 hp; hp.x = h0; hp.y = h1;
                    *(__nv_bfloat162*)&Cvh[o] = hp;
                    __nv_bfloat162 lp;
                    lp.x = __float2bfloat16(v.x - __bfloat162float(h0));
                    lp.y = __float2bfloat16(v.y - __bfloat162float(h1));
                    *(__nv_bfloat162*)&Cvl[o] = lp;
                }
            }
        }
    }
}

// ============================================================
// Feature kernel with fused RoPE -> bf16 hi/lo u and w rows [n][80]
// ============================================================
__global__ void feature_kernel(const float* __restrict__ q, const float* __restrict__ k,
                               const float* __restrict__ ct, const float* __restrict__ st,
                               const float* __restrict__ Wqm, const float* __restrict__ Wkm,
                               const float* __restrict__ Wm,
                               __nv_bfloat16* __restrict__ uhg, __nv_bfloat16* __restrict__ ulg,
                               __nv_bfloat16* __restrict__ whg, __nv_bfloat16* __restrict__ wlg)
{
    __shared__ float sWqm[512], sWkm[512], sWm[512];
    __shared__ float sOut[64][81];

    int tid = threadIdx.x;           // 64 threads
    int n0 = blockIdx.x * 64;
    int n  = n0 + tid;
    int t  = n & 1023;

    for (int p = tid; p < 512; p += 64) {
        sWqm[p] = Wqm[p]; sWkm[p] = Wkm[p]; sWm[p] = Wm[p];
    }
    __syncthreads();

    const float4* qr = (const float4*)(q + (size_t)n*64);
    const float4* kr = (const float4*)(k + (size_t)n*64);
    const float4* cp4 = (const float4*)(ct + (size_t)t*32);
    const float4* sp4 = (const float4*)(st + (size_t)t*32);

    float qm[8], km[8];
    #pragma unroll
    for (int m = 0; m < 8; m++) { qm[m] = 0.f; km[m] = 0.f; }
    #pragma unroll
    for (int d4 = 0; d4 < 8; d4++) {
        float4 q1 = qr[d4], q2 = qr[d4+8];
        float4 k1 = kr[d4], k2 = kr[d4+8];
        float4 cv = cp4[d4], sv = sp4[d4];
        const float* q1f = (const float*)&q1;
        const float* q2f = (const float*)&q2;
        const float* k1f = (const float*)&k1;
        const float* k2f = (const float*)&k2;
        const float* cf  = (const float*)&cv;
        const float* sf  = (const float*)&sv;
        #pragma unroll
        for (int j = 0; j < 4; j++) {
            int i = d4*4 + j;
            float c = cf[j], s = sf[j];
            float qa = q1f[j]*c - q2f[j]*s;
            float qb = q1f[j]*s + q2f[j]*c;
            float ka = k1f[j]*c - k2f[j]*s;
            float kb = k1f[j]*s + k2f[j]*c;
            #pragma unroll
            for (int m = 0; m < 8; m++) {
                qm[m] = fmaf(qa, sWqm[i*8+m], fmaf(qb, sWqm[(i+32)*8+m], qm[m]));
                km[m] = fmaf(ka, sWkm[i*8+m], fmaf(kb, sWkm[(i+32)*8+m], km[m]));
            }
        }
    }
    #pragma unroll
    for (int m = 0; m < 8; m++) {
        qm[m] = 1.0f / (1.0f + expf(-qm[m]));
        km[m] = 1.0f / (1.0f + expf(-km[m]));
    }

    float A[64];
    #pragma unroll
    for (int nn = 0; nn < 64; nn++) {
        float s = 0.f;
        #pragma unroll
        for (int m = 0; m < 8; m++) s = fmaf(qm[m], sWm[m*64+nn], s);
        A[nn] = s;
    }

    float Gq[8];
    #pragma unroll
    for (int d = 0; d < 8; d++) Gq[d] = 0.f;
    #pragma unroll
    for (int d = 0; d < 8; d++) {
        #pragma unroll
        for (int f = 0; f < 8; f++) {
            float g = 0.f;
            #pragma unroll
            for (int e = 0; e < 8; e++) g = fmaf(A[d*8+e], A[f*8+e], g);
            if (d == f) g += EPS_PSD;
            Gq[d] = fmaf(g, qm[f], Gq[d]);
            sOut[tid][8 + d*8 + f] = -g;
        }
    }
    float qGq = 0.f;
    #pragma unroll
    for (int d = 0; d < 8; d++) {
        qGq = fmaf(Gq[d], qm[d], qGq);
        sOut[tid][d] = 2.0f * Gq[d];
    }
    sOut[tid][72] = -qGq;
    #pragma unroll
    for (int p = 73; p < 80; p++) sOut[tid][p] = 0.f;
    __syncthreads();

    for (int p = tid; p < 64*80; p += 64) {
        int r = p / 80, c = p % 80;
        float v = sOut[r][c];
        __nv_bfloat16 h = __float2bfloat16(v);
        size_t o = (size_t)(n0 + r)*UDIM + c;
        uhg[o] = h;
        ulg[o] = __float2bfloat16(v - __bfloat162float(h));
    }
    __syncthreads();

    #pragma unroll
    for (int d = 0; d < 8; d++) sOut[tid][d] = km[d];
    #pragma unroll
    for (int d = 0; d < 8; d++)
        #pragma unroll
        for (int f = 0; f < 8; f++)
            sOut[tid][8 + d*8 + f] = km[d]*km[f];
    sOut[tid][72] = 1.0f;
    #pragma unroll
    for (int p = 73; p < 80; p++) sOut[tid][p] = 0.f;
    __syncthreads();

    for (int p = tid; p < 64*80; p += 64) {
        int r = p / 80, c = p % 80;
        float v = sOut[r][c];
        __nv_bfloat16 h = __float2bfloat16(v);
        size_t o = (size_t)(n0 + r)*UDIM + c;
        whg[o] = h;
        wlg[o] = __float2bfloat16(v - __bfloat162float(h));
    }
}

// ============================================================
// Tensor-core flash: S = U.W^T (bf16x3), P = exp(min(S,0)/temp)
// (S<=0 always, no max tracking), O = P.V (bf16x3), split-k over warp_n.
// 64x64 tiles, 8 warps; 2-stage cp.async, single sync per tile.
// ============================================================
#define FL_USTR 88
#define FL_VSTR 72
#define FL_OFF_UL (64*FL_USTR*2)            // 11264
#define FL_OFF_W  (2*64*FL_USTR*2)          // 22528
#define FL_WBUF   (2*64*FL_USTR*2)          // 22528
#define FL_OFF_V  (FL_OFF_W + 2*FL_WBUF)    // 67584
#define FL_VBUF   (2*64*FL_VSTR*2)          // 18432
#define FLASH_SMEM (FL_OFF_V + 2*FL_VBUF)   // 104448

__global__ __launch_bounds__(256, 1)
void flash_mma(const __nv_bfloat16* __restrict__ uh, const __nv_bfloat16* __restrict__ ul,
               const __nv_bfloat16* __restrict__ wh, const __nv_bfloat16* __restrict__ wl,
               const __nv_bfloat16* __restrict__ vh, const __nv_bfloat16* __restrict__ vl,
               __nv_bfloat16* __restrict__ oh, __nv_bfloat16* __restrict__ ol,
               const float* __restrict__ temperature)
{
    extern __shared__ char smem[];
    uint32_t sb = smem_u32(smem);
    int tid = threadIdx.x, wid = tid >> 5, lane = tid & 31;
    int warp_m = wid & 1, warp_n = wid >> 1;
    int bh = blockIdx.y;
    int ib = (int)(gridDim.x - 1 - blockIdx.x);
    float inv_temp = 1.f / fmaxf(temperature[0], 0.1f);

    // U tile load (joins first commit group)
    {
        const char* gh = (const char*)(uh + (size_t)(bh*SEQ + ib*64)*UDIM);
        const char* gl = (const char*)(ul + (size_t)(bh*SEQ + ib*64)*UDIM);
        for (int p = tid; p < 640; p += 256) {
            int r = p / 10, c = p % 10;
            CP_ASYNC16(sb + r*(FL_USTR*2) + c*16, gh + r*160 + c*16);
            CP_ASYNC16(sb + FL_OFF_UL + r*(FL_USTR*2) + c*16, gl + r*160 + c*16);
        }
    }
    #define ISSUE_WV(jb, buf) do { \
        const char* gwh = (const char*)(wh + (size_t)(bh*SEQ + (jb)*64)*UDIM); \
        const char* gwl = (const char*)(wl + (size_t)(bh*SEQ + (jb)*64)*UDIM); \
        uint32_t wdst = sb + FL_OFF_W + (buf)*FL_WBUF; \
        for (int p = tid; p < 640; p += 256) { \
            int r = p / 10, c = p % 10; \
            CP_ASYNC16(wdst + r*176 + c*16, gwh + r*160 + c*16); \
            CP_ASYNC16(wdst + 11264 + r*176 + c*16, gwl + r*160 + c*16); \
        } \
        const char* gvh = (const char*)(vh + (size_t)(bh*SEQ + (jb)*64)*DHEAD); \
        const char* gvl = (const char*)(vl + (size_t)(bh*SEQ + (jb)*64)*DHEAD); \
        uint32_t vdst = sb + FL_OFF_V + (buf)*FL_VBUF; \
        for (int p = tid; p < 512; p += 256) { \
            int r = p / 8, c = p % 8; \
            CP_ASYNC16(vdst + r*144 + c*16, gvh + r*128 + c*16); \
            CP_ASYNC16(vdst + 9216 + r*144 + c*16, gvl + r*128 + c*16); \
        } \
    } while (0)

    ISSUE_WV(0, 0);
    CP_COMMIT();

    float accO[2][8][4];
    float l_acc[4];
    #pragma unroll
    for (int i = 0; i < 4; i++) l_acc[i] = 0.f;
    #pragma unroll
    for (int mt = 0; mt < 2; mt++)
        #pragma unroll
        for (int nt = 0; nt < 8; nt++)
            #pragma unroll
            for (int r = 0; r < 4; r++) accO[mt][nt][r] = 0.f;

    for (int jb = 0; jb <= ib; jb++) {
        int buf = jb & 1;
        CP_WAIT(0);
        __syncthreads();           // data visible + protects buf^1 (computed last iter)
        if (jb < ib) { ISSUE_WV(jb+1, buf^1); CP_COMMIT(); }

        uint32_t sw_h = sb + FL_OFF_W + buf*FL_WBUF;
        uint32_t sw_l = sw_h + 11264;
        uint32_t sv_h = sb + FL_OFF_V + buf*FL_VBUF;
        uint32_t sv_l = sv_h + 9216;

        // ---- S = U . W^T ----
        float sc[2][2][4];
        #pragma unroll
        for (int mt = 0; mt < 2; mt++)
            #pragma unroll
            for (int nt = 0; nt < 2; nt++)
                #pragma unroll
                for (int r = 0; r < 4; r++) sc[mt][nt][r] = 0.f;

        #pragma unroll
        for (int k5 = 0; k5 < 5; k5++) {
            int k0 = k5*16;
            uint32_t a_h[2][4], a_l[2][4], b_h[2][2], b_l[2][2];
            #pragma unroll
            for (int mt = 0; mt < 2; mt++) {
                int row = warp_m*32 + mt*16 + (lane & 15);
                uint32_t off = (uint32_t)(row*FL_USTR + k0 + ((lane >> 4) << 3))*2;
                ldmatrix_x4(a_h[mt], sb + off);
                ldmatrix_x4(a_l[mt], sb + FL_OFF_UL + off);
            }
            #pragma unroll
            for (int nt = 0; nt < 2; nt++) {
                int row = warp_n*16 + nt*8 + (lane & 7);
                uint32_t off = (uint32_t)(row*FL_USTR + k0 + (((lane >> 3) & 1) << 3))*2;
                ldmatrix_x2(b_h[nt], sw_h + off);
                ldmatrix_x2(b_l[nt], sw_l + off);
            }
            #pragma unroll
            for (int mt = 0; mt < 2; mt++)
                #pragma unroll
                for (int nt = 0; nt < 2; nt++)
                    mma16816(sc[mt][nt], a_h[mt], b_h[nt]);
            #pragma unroll
            for (int mt = 0; mt < 2; mt++)
                #pragma unroll
                for (int nt = 0; nt < 2; nt++)
                    mma16816(sc[mt][nt], a_h[mt], b_l[nt]);
            #pragma unroll
            for (int mt = 0; mt < 2; mt++)
                #pragma unroll
                for (int nt = 0; nt < 2; nt++)
                    mma16816(sc[mt][nt], a_l[mt], b_h[nt]);
        }

        // ---- P = exp(min(S,0)/temp), causal mask, row-sum partials ----
        bool diag = (jb == ib);
        uint32_t ph[2][4], pl[2][4];
        #pragma unroll
        for (int mt = 0; mt < 2; mt++) {
            #pragma unroll
            for (int half = 0; half < 2; half++) {
                int t_g = ib*64 + warp_m*32 + mt*16 + (lane >> 2) + half*8;
                float pv[4];
                #pragma unroll
                for (int nt = 0; nt < 2; nt++) {
                    #pragma unroll
                    for (int cc = 0; cc < 2; cc++) {
                        int s_g = jb*64 + warp_n*16 + nt*8 + (lane & 3)*2 + cc;
                        float v = sc[mt][nt][half*2 + cc];
                        float p = __expf(fminf(v, 0.f) * inv_temp);
                        if (diag && s_g > t_g) p = 0.f;
                        pv[nt*2 + cc] = p;
                    }
                }
                float ls = pv[0] + pv[1] + pv[2] + pv[3];
                ls += __shfl_xor_sync(0xffffffffu, ls, 1);
                ls += __shfl_xor_sync(0xffffffffu, ls, 2);
                l_acc[mt*2 + half] += ls;
                split2(pv[0], pv[1], ph[mt][half], pl[mt][half]);
                split2(pv[2], pv[3], ph[mt][2 + half], pl[mt][2 + half]);
            }
        }

        // ---- O += P . V  (k-slice = warp_n's 16 s) ----
        #pragma unroll
        for (int ntp = 0; ntp < 4; ntp++) {
            uint32_t v_h[2][2], v_l[2][2];
            #pragma unroll
            for (int q2 = 0; q2 < 2; q2++) {
                int nt = ntp*2 + q2;
                uint32_t off = (uint32_t)((warp_n*16 + (lane & 15))*FL_VSTR + nt*8)*2;
                ldmatrix_x2_trans(v_h[q2], sv_h + off);
                ldmatrix_x2_trans(v_l[q2], sv_l + off);
            }
            #pragma unroll
            for (int mt = 0; mt < 2; mt++)
                #pragma unroll
                for (int q2 = 0; q2 < 2; q2++)
                    mma16816(accO[mt][ntp*2+q2], ph[mt], v_h[q2]);
            #pragma unroll
            for (int mt = 0; mt < 2; mt++)
                #pragma unroll
                for (int q2 = 0; q2 < 2; q2++)
                    mma16816(accO[mt][ntp*2+q2], ph[mt], v_l[q2]);
            #pragma unroll
            for (int mt = 0; mt < 2; mt++)
                #pragma unroll
                for (int q2 = 0; q2 < 2; q2++)
                    mma16816(accO[mt][ntp*2+q2], pl[mt], v_h[q2]);
        }
    }
    __syncthreads();   // last tile's ldmatrix done before smem reuse below

    // ---- cross-warp_n reduction (staged, reuses U region) ----
    float* sO   = (float*)smem;                 // [64][66]
    float* lred = (float*)(smem + 64*66*4);     // [64]
    #pragma unroll 1
    for (int stage = 0; stage < 4; stage++) {
        if (warp_n == stage) {
            #pragma unroll
            for (int mt = 0; mt < 2; mt++) {
                #pragma unroll
                for (int half = 0; half < 2; half++) {
                    int r = warp_m*32 + mt*16 + (lane >> 2) + half*8;
                    #pragma unroll
                    for (int nt = 0; nt < 8; nt++) {
                        int cc = nt*8 + (lane & 3)*2;
                        float v0 = accO[mt][nt][half*2 + 0];
                        float v1 = accO[mt][nt][half*2 + 1];
                        if (stage == 0) { sO[r*66+cc] = v0; sO[r*66+cc+1] = v1; }
                        else            { sO[r*66+cc] += v0; sO[r*66+cc+1] += v1; }
                    }
                    if ((lane & 3) == 0) {
                        if (stage == 0) lred[r] = l_acc[mt*2 + half];
                        else            lred[r] += l_acc[mt*2 + half];
                    }
                }
            }
        }
        __syncthreads();
    }

    // ---- normalize + write bf16 hi/lo token-major ----
    int b = bh >> 4, h = bh & 15;
    for (int p = tid; p < 4096; p += 256) {
        int t = p >> 6, d = p & 63;
        float v = sO[t*66 + d] / lred[t];
        __nv_bfloat16 hv = __float2bfloat16(v);
        size_t o = ((size_t)(b*SEQ + ib*64 + t))*DMODEL + h*64 + d;
        oh[o] = hv;
        ol[o] = __float2bfloat16(v - __bfloat162float(hv));
    }
}

// ============================================================
extern "C" void kernel_launch(void* const* d_in, const int* in_sizes, int n_in,
                              void* d_out, int out_size)
{
    (void)in_sizes; (void)n_in; (void)out_size;
    const float* x    = (const float*)d_in[0];
    const float* Wq   = (const float*)d_in[1];
    const float* Wk   = (const float*)d_in[2];
    const float* Wv   = (const float*)d_in[3];
    const float* Wo   = (const float*)d_in[4];
    const float* Wqm  = (const float*)d_in[5];
    const float* Wkm  = (const float*)d_in[6];
    const float* Wm   = (const float*)d_in[7];
    const float* temp = (const float*)d_in[8];

    float *q, *k, *ct, *st;
    __nv_bfloat16 *xh, *xl, *wth, *wtl, *vh, *vl, *uh, *ul, *wwh, *wwl, *a2h, *a2l;
    cudaGetSymbolAddress((void**)&q,   g_q);
    cudaGetSymbolAddress((void**)&k,   g_k);
    cudaGetSymbolAddress((void**)&ct,  g_cos);
    cudaGetSymbolAddress((void**)&st,  g_sin);
    cudaGetSymbolAddress((void**)&xh,  g_xh);
    cudaGetSymbolAddress((void**)&xl,  g_xl);
    cudaGetSymbolAddress((void**)&wth, g_wth);
    cudaGetSymbolAddress((void**)&wtl, g_wtl);
    cudaGetSymbolAddress((void**)&vh,  g_vh);
    cudaGetSymbolAddress((void**)&vl,  g_vl);
    cudaGetSymbolAddress((void**)&uh,  g_uh);
    cudaGetSymbolAddress((void**)&ul,  g_ul);
    cudaGetSymbolAddress((void**)&wwh, g_wh);
    cudaGetSymbolAddress((void**)&wwl, g_wl);
    cudaGetSymbolAddress((void**)&a2h, g_a2h);
    cudaGetSymbolAddress((void**)&a2l, g_a2l);

    cudaFuncSetAttribute(mma_gemm<0>, cudaFuncAttributeMaxDynamicSharedMemorySize, GEMM_SMEM);
    cudaFuncSetAttribute(mma_gemm<1>, cudaFuncAttributeMaxDynamicSharedMemorySize, GEMM_SMEM);
    cudaFuncSetAttribute(flash_mma,  cudaFuncAttributeMaxDynamicSharedMemorySize, FLASH_SMEM);

    rope_table_kernel<<<(SEQ*32)/256, 256>>>(ct, st);
    wconv_kernel<<<dim3(32, 32, 4), dim3(32, 8)>>>(Wq, Wk, Wv, Wo, wth, wtl);
    xconv_kernel<<<(NTOK*DMODEL)/256, 256>>>(x, xh, xl);

    // fused QKV (z=0 q, z=1 k f32 scatter; z=2 v bf16 hi/lo)
    size_t WSZ = (size_t)DMODEL*DMODEL;
    mma_gemm<1><<<dim3(DMODEL/128, NTOK/128, 3), 256, GEMM_SMEM>>>(
        xh, xl, wth, wtl, q, k, vh, vl);

    feature_kernel<<<NBHT/64, 64>>>(q, k, ct, st, Wqm, Wkm, Wm, uh, ul, wwh, wwl);

    flash_mma<<<dim3(SEQ/64, BATCH*NHEADS), 256, FLASH_SMEM>>>(
        uh, ul, wwh, wwl, vh, vl, a2h, a2l, temp);

    mma_gemm<0><<<dim3(DMODEL/128, NTOK/128, 1), 256, GEMM_SMEM>>>(
        a2h, a2l, wth + 3*WSZ, wtl + 3*WSZ, (float*)d_out,
        nullptr, nullptr, nullptr);
}

// round 6
// speedup vs baseline: 2.5493x; 1.0370x over previous
#include <cuda_runtime.h>
#include <cuda_bf16.h>
#include <math.h>
#include <stdint.h>

// Problem constants
#define BATCH   2
#define SEQ     1024
#define DMODEL  1024
#define NHEADS  16
#define DHEAD   64
#define NTOK    (BATCH*SEQ)          // 2048
#define NBHT    (BATCH*NHEADS*SEQ)   // 32768
#define UDIM    80                   // 73 padded to 80
#define EPS_PSD 0.001f

// -------- device scratch (static, no allocations) --------
__device__ float g_q[NBHT*DHEAD];
__device__ float g_k[NBHT*DHEAD];
__device__ float g_cos[SEQ*32];
__device__ float g_sin[SEQ*32];

__device__ __nv_bfloat16 g_xh[NTOK*DMODEL];
__device__ __nv_bfloat16 g_xl[NTOK*DMODEL];
__device__ __nv_bfloat16 g_wth[4*DMODEL*DMODEL]; // Wq,Wk,Wv,Wo transposed [n][k]
__device__ __nv_bfloat16 g_wtl[4*DMODEL*DMODEL];

__device__ __nv_bfloat16 g_vh[NBHT*DHEAD];       // V bf16 hi/lo [bh][t][d]
__device__ __nv_bfloat16 g_vl[NBHT*DHEAD];

__device__ __nv_bfloat16 g_uh[NBHT*UDIM];        // u rows bf16 hi/lo [n][80]
__device__ __nv_bfloat16 g_ul[NBHT*UDIM];
__device__ __nv_bfloat16 g_wh[NBHT*UDIM];        // w rows bf16 hi/lo [n][80]
__device__ __nv_bfloat16 g_wl[NBHT*UDIM];

__device__ __nv_bfloat16 g_a2h[NTOK*DMODEL];     // attention out, token-major
__device__ __nv_bfloat16 g_a2l[NTOK*DMODEL];

// ============================================================
// PTX helpers
// ============================================================
__device__ __forceinline__ uint32_t smem_u32(const void* p) {
    uint32_t a;
    asm("{ .reg .u64 t; cvta.to.shared.u64 t, %1; cvt.u32.u64 %0, t; }" : "=r"(a) : "l"(p));
    return a;
}
__device__ __forceinline__ void ldmatrix_x4(uint32_t* r, uint32_t addr) {
    asm volatile("ldmatrix.sync.aligned.m8n8.x4.shared.b16 {%0,%1,%2,%3}, [%4];"
        : "=r"(r[0]), "=r"(r[1]), "=r"(r[2]), "=r"(r[3]) : "r"(addr));
}
__device__ __forceinline__ void ldmatrix_x2(uint32_t* r, uint32_t addr) {
    asm volatile("ldmatrix.sync.aligned.m8n8.x2.shared.b16 {%0,%1}, [%2];"
        : "=r"(r[0]), "=r"(r[1]) : "r"(addr));
}
__device__ __forceinline__ void ldmatrix_x2_trans(uint32_t* r, uint32_t addr) {
    asm volatile("ldmatrix.sync.aligned.m8n8.x2.trans.shared.b16 {%0,%1}, [%2];"
        : "=r"(r[0]), "=r"(r[1]) : "r"(addr));
}
__device__ __forceinline__ void mma16816(float* c, const uint32_t* a, const uint32_t* b) {
    asm volatile("mma.sync.aligned.m16n8k16.row.col.f32.bf16.bf16.f32 "
        "{%0,%1,%2,%3}, {%4,%5,%6,%7}, {%8,%9}, {%0,%1,%2,%3};"
        : "+f"(c[0]), "+f"(c[1]), "+f"(c[2]), "+f"(c[3])
        : "r"(a[0]), "r"(a[1]), "r"(a[2]), "r"(a[3]), "r"(b[0]), "r"(b[1]));
}
#define CP_ASYNC16(saddr, gptr) \
    asm volatile("cp.async.cg.shared.global [%0], [%1], 16;" \
        :: "r"(saddr), "l"(gptr) : "memory")
#define CP_COMMIT() asm volatile("cp.async.commit_group;" ::: "memory")
#define CP_WAIT(N)  asm volatile("cp.async.wait_group %0;" :: "n"(N) : "memory")

__device__ __forceinline__ void split2(float v0, float v1, uint32_t& h, uint32_t& l) {
    __nv_bfloat16 h0 = __float2bfloat16(v0), h1 = __float2bfloat16(v1);
    __nv_bfloat162 hp; hp.x = h0; hp.y = h1;
    h = *(uint32_t*)&hp;
    __nv_bfloat16 l0 = __float2bfloat16(v0 - __bfloat162float(h0));
    __nv_bfloat16 l1 = __float2bfloat16(v1 - __bfloat162float(h1));
    __nv_bfloat162 lp; lp.x = l0; lp.y = l1;
    l = *(uint32_t*)&lp;
}

// ============================================================
// Conversion + table kernels
// ============================================================
__global__ void xconv_kernel(const float* __restrict__ x,
                             __nv_bfloat16* __restrict__ xh,
                             __nv_bfloat16* __restrict__ xl)
{
    int i = blockIdx.x * blockDim.x + threadIdx.x;
    if (i >= NTOK*DMODEL) return;
    float v = x[i];
    __nv_bfloat16 h = __float2bfloat16(v);
    xh[i] = h;
    xl[i] = __float2bfloat16(v - __bfloat162float(h));
}

__global__ void wconv_kernel(const float* __restrict__ W0, const float* __restrict__ W1,
                             const float* __restrict__ W2, const float* __restrict__ W3,
                             __nv_bfloat16* __restrict__ th, __nv_bfloat16* __restrict__ tl)
{
    __shared__ float s[32][33];
    const float* W = (blockIdx.z == 0) ? W0 : (blockIdx.z == 1) ? W1
                   : (blockIdx.z == 2) ? W2 : W3;
    size_t zoff = (size_t)blockIdx.z * DMODEL * DMODEL;
    int n0 = blockIdx.x * 32, k0 = blockIdx.y * 32;
    int tx = threadIdx.x, ty = threadIdx.y;   // 32 x 8
    #pragma unroll
    for (int j = 0; j < 4; j++)
        s[ty + j*8][tx] = W[(size_t)(k0 + ty + j*8)*DMODEL + n0 + tx];
    __syncthreads();
    #pragma unroll
    for (int j = 0; j < 4; j++) {
        float v = s[tx][ty + j*8];
        __nv_bfloat16 h = __float2bfloat16(v);
        size_t o = zoff + (size_t)(n0 + ty + j*8)*DMODEL + k0 + tx;
        th[o] = h;
        tl[o] = __float2bfloat16(v - __bfloat162float(h));
    }
}

__global__ void rope_table_kernel(float* __restrict__ ct, float* __restrict__ st)
{
    int idx = blockIdx.x * blockDim.x + threadIdx.x;
    if (idx >= SEQ*32) return;
    int i = idx & 31, t = idx >> 5;
    float inv = (float)(1.0 / pow(10000.0, (double)i / 32.0));
    float ang = (float)t * inv;
    float s, c;
    sincosf(ang, &s, &c);
    ct[idx] = c;
    st[idx] = s;
}

// ============================================================
// mma.sync bf16x3 GEMM, 128x64 CTA tile, 8 warps (2m x 4n),
// warp = 64x16 via 4x2 m16n8k16; variant-outer order; 3-stage
// cp.async pipeline; __launch_bounds__(256,2) for 2 CTAs/SM.
// MODE 0: plain f32 out.  MODE 1: fused QKV (z: 0=q,1=k f32 scatter; 2=v bf16 hl).
// ============================================================
#define KC 32
#define ROW_STRIDE 40
#define MAT_A_BYTES (128*ROW_STRIDE*2)     // 10240
#define MAT_B_BYTES (64*ROW_STRIDE*2)      // 5120
#define STAGE_BYTES (2*MAT_A_BYTES + 2*MAT_B_BYTES)  // 30720
#define GEMM_SMEM (3*STAGE_BYTES)          // 92160

template<int MODE>
__global__ __launch_bounds__(256, 2)
void mma_gemm(const __nv_bfloat16* __restrict__ Ah, const __nv_bfloat16* __restrict__ Al,
              const __nv_bfloat16* __restrict__ Bh0, const __nv_bfloat16* __restrict__ Bl0,
              float* __restrict__ C0, float* __restrict__ C1,
              __nv_bfloat16* __restrict__ Cvh, __nv_bfloat16* __restrict__ Cvl)
{
    extern __shared__ char smem[];
    uint32_t sbase = smem_u32(smem);
    int tid = threadIdx.x, wid = tid >> 5, lane = tid & 31;
    int n0 = blockIdx.x * 64, m0 = blockIdx.y * 128;
    int z = (MODE == 1) ? blockIdx.z : 0;

    const __nv_bfloat16* Bh = Bh0 + (size_t)z * DMODEL * DMODEL;
    const __nv_bfloat16* Bl = Bl0 + (size_t)z * DMODEL * DMODEL;

    int mat = tid >> 6;        // 0=Ah 1=Al 2=Bh 3=Bl
    int tp  = tid & 63;
    const __nv_bfloat16* gsrc =
        (mat == 0) ? Ah + (size_t)m0*DMODEL :
        (mat == 1) ? Al + (size_t)m0*DMODEL :
        (mat == 2) ? Bh + (size_t)n0*DMODEL :
                     Bl + (size_t)n0*DMODEL;
    uint32_t moff = (mat < 2) ? (uint32_t)mat*MAT_A_BYTES
                              : (uint32_t)(2*MAT_A_BYTES + (mat-2)*MAT_B_BYTES);
    int niter = (mat < 2) ? 8 : 4;

    int warp_m = wid & 1, warp_n = wid >> 1;

    float acc[4][2][4];
    #pragma unroll
    for (int a = 0; a < 4; a++)
        #pragma unroll
        for (int b = 0; b < 2; b++)
            #pragma unroll
            for (int c = 0; c < 4; c++) acc[a][b][c] = 0.f;

    #define GEMM_ISSUE(chunk, slot) do { \
        const __nv_bfloat16* g = gsrc + (chunk)*KC; \
        uint32_t sdst = sbase + (slot)*STAGE_BYTES + moff; \
        for (int it = 0; it < niter; it++) { \
            int idx = tp + it*64; \
            int row = idx >> 2, c4 = idx & 3; \
            CP_ASYNC16(sdst + row*(ROW_STRIDE*2) + c4*16, \
                       g + (size_t)row*DMODEL + c4*8); \
        } \
        CP_COMMIT(); \
    } while (0)

    GEMM_ISSUE(0, 0);
    GEMM_ISSUE(1, 1);

    for (int c = 0; c < DMODEL/KC; c++) {
        int slot = c % 3;
        if (c < DMODEL/KC - 1) CP_WAIT(1); else CP_WAIT(0);
        __syncthreads();
        if (c + 2 < DMODEL/KC) GEMM_ISSUE(c + 2, (c + 2) % 3);

        uint32_t b_off = sbase + slot*STAGE_BYTES;
        #pragma unroll
        for (int ks = 0; ks < 2; ks++) {
            int k0 = ks * 16;
            uint32_t a_h[4][4], a_l[4][4], b_h[2][2], b_l[2][2];
            #pragma unroll
            for (int mt = 0; mt < 4; mt++) {
                int row = warp_m*64 + mt*16 + (lane & 15);
                uint32_t col = k0 + ((lane >> 4) << 3);
                uint32_t off = b_off + (row*ROW_STRIDE + col)*2;
                ldmatrix_x4(a_h[mt], off);
                ldmatrix_x4(a_l[mt], off + MAT_A_BYTES);
            }
            #pragma unroll
            for (int nt = 0; nt < 2; nt++) {
                int row = warp_n*16 + nt*8 + (lane & 7);
                uint32_t col = k0 + (((lane >> 3) & 1) << 3);
                uint32_t off = b_off + 2*MAT_A_BYTES + (row*ROW_STRIDE + col)*2;
                ldmatrix_x2(b_h[nt], off);
                ldmatrix_x2(b_l[nt], off + MAT_B_BYTES);
            }
            #pragma unroll
            for (int mt = 0; mt < 4; mt++)
                #pragma unroll
                for (int nt = 0; nt < 2; nt++)
                    mma16816(acc[mt][nt], a_h[mt], b_h[nt]);
            #pragma unroll
            for (int mt = 0; mt < 4; mt++)
                #pragma unroll
                for (int nt = 0; nt < 2; nt++)
                    mma16816(acc[mt][nt], a_h[mt], b_l[nt]);
            #pragma unroll
            for (int mt = 0; mt < 4; mt++)
                #pragma unroll
                for (int nt = 0; nt < 2; nt++)
                    mma16816(acc[mt][nt], a_l[mt], b_h[nt]);
        }
    }

    // epilogue
    int qrow = lane >> 2, qcol = (lane & 3) * 2;
    #pragma unroll
    for (int mt = 0; mt < 4; mt++) {
        #pragma unroll
        for (int nt = 0; nt < 2; nt++) {
            int row0 = m0 + warp_m*64 + mt*16 + qrow;
            int col  = n0 + warp_n*16 + nt*8 + qcol;
            float2 v0 = make_float2(acc[mt][nt][0], acc[mt][nt][1]);
            float2 v1 = make_float2(acc[mt][nt][2], acc[mt][nt][3]);
            if (MODE == 0) {
                *(float2*)&C0[(size_t)row0*DMODEL + col] = v0;
                *(float2*)&C0[(size_t)(row0 + 8)*DMODEL + col] = v1;
            } else if (z < 2) {
                float* C = z ? C1 : C0;
                int h = col >> 6, d = col & 63;
                int b0 = row0 >> 10, t0 = row0 & 1023;
                *(float2*)&C[((size_t)((b0*NHEADS + h)*SEQ + t0))*DHEAD + d] = v0;
                int r1 = row0 + 8;
                int b1 = r1 >> 10, t1 = r1 & 1023;
                *(float2*)&C[((size_t)((b1*NHEADS + h)*SEQ + t1))*DHEAD + d] = v1;
            } else {
                int h = col >> 6, d = col & 63;
                #pragma unroll
                for (int rr = 0; rr < 2; rr++) {
                    int row = row0 + rr*8;
                    float2 v = rr ? v1 : v0;
                    int b = row >> 10, t = row & 1023;
                    size_t o = ((size_t)((b*NHEADS + h)*SEQ + t))*DHEAD + d;
                    __nv_bfloat16 h0 = __float2bfloat16(v.x), h1 = __float2bfloat16(v.y);
                    __nv_bfloat162 hp; hp.x = h0; hp.y = h1;
                    *(__nv_bfloat162*)&Cvh[o] = hp;
                    __nv_bfloat162 lp;
                    lp.x = __float2bfloat16(v.x - __bfloat162float(h0));
                    lp.y = __float2bfloat16(v.y - __bfloat162float(h1));
                    *(__nv_bfloat162*)&Cvl[o] = lp;
                }
            }
        }
    }
}

// ============================================================
// Feature kernel with fused RoPE -> bf16 hi/lo u and w rows [n][80]
// ============================================================
__global__ void feature_kernel(const float* __restrict__ q, const float* __restrict__ k,
                               const float* __restrict__ ct, const float* __restrict__ st,
                               const float* __restrict__ Wqm, const float* __restrict__ Wkm,
                               const float* __restrict__ Wm,
                               __nv_bfloat16* __restrict__ uhg, __nv_bfloat16* __restrict__ ulg,
                               __nv_bfloat16* __restrict__ whg, __nv_bfloat16* __restrict__ wlg)
{
    __shared__ float sWqm[512], sWkm[512], sWm[512];
    __shared__ float sOut[64][81];

    int tid = threadIdx.x;           // 64 threads
    int n0 = blockIdx.x * 64;
    int n  = n0 + tid;
    int t  = n & 1023;

    for (int p = tid; p < 512; p += 64) {
        sWqm[p] = Wqm[p]; sWkm[p] = Wkm[p]; sWm[p] = Wm[p];
    }
    __syncthreads();

    const float4* qr = (const float4*)(q + (size_t)n*64);
    const float4* kr = (const float4*)(k + (size_t)n*64);
    const float4* cp4 = (const float4*)(ct + (size_t)t*32);
    const float4* sp4 = (const float4*)(st + (size_t)t*32);

    float qm[8], km[8];
    #pragma unroll
    for (int m = 0; m < 8; m++) { qm[m] = 0.f; km[m] = 0.f; }
    #pragma unroll
    for (int d4 = 0; d4 < 8; d4++) {
        float4 q1 = qr[d4], q2 = qr[d4+8];
        float4 k1 = kr[d4], k2 = kr[d4+8];
        float4 cv = cp4[d4], sv = sp4[d4];
        const float* q1f = (const float*)&q1;
        const float* q2f = (const float*)&q2;
        const float* k1f = (const float*)&k1;
        const float* k2f = (const float*)&k2;
        const float* cf  = (const float*)&cv;
        const float* sf  = (const float*)&sv;
        #pragma unroll
        for (int j = 0; j < 4; j++) {
            int i = d4*4 + j;
            float c = cf[j], s = sf[j];
            float qa = q1f[j]*c - q2f[j]*s;
            float qb = q1f[j]*s + q2f[j]*c;
            float ka = k1f[j]*c - k2f[j]*s;
            float kb = k1f[j]*s + k2f[j]*c;
            #pragma unroll
            for (int m = 0; m < 8; m++) {
                qm[m] = fmaf(qa, sWqm[i*8+m], fmaf(qb, sWqm[(i+32)*8+m], qm[m]));
                km[m] = fmaf(ka, sWkm[i*8+m], fmaf(kb, sWkm[(i+32)*8+m], km[m]));
            }
        }
    }
    #pragma unroll
    for (int m = 0; m < 8; m++) {
        qm[m] = 1.0f / (1.0f + expf(-qm[m]));
        km[m] = 1.0f / (1.0f + expf(-km[m]));
    }

    float A[64];
    #pragma unroll
    for (int nn = 0; nn < 64; nn++) {
        float s = 0.f;
        #pragma unroll
        for (int m = 0; m < 8; m++) s = fmaf(qm[m], sWm[m*64+nn], s);
        A[nn] = s;
    }

    float Gq[8];
    #pragma unroll
    for (int d = 0; d < 8; d++) Gq[d] = 0.f;
    #pragma unroll
    for (int d = 0; d < 8; d++) {
        #pragma unroll
        for (int f = 0; f < 8; f++) {
            float g = 0.f;
            #pragma unroll
            for (int e = 0; e < 8; e++) g = fmaf(A[d*8+e], A[f*8+e], g);
            if (d == f) g += EPS_PSD;
            Gq[d] = fmaf(g, qm[f], Gq[d]);
            sOut[tid][8 + d*8 + f] = -g;
        }
    }
    float qGq = 0.f;
    #pragma unroll
    for (int d = 0; d < 8; d++) {
        qGq = fmaf(Gq[d], qm[d], qGq);
        sOut[tid][d] = 2.0f * Gq[d];
    }
    sOut[tid][72] = -qGq;
    #pragma unroll
    for (int p = 73; p < 80; p++) sOut[tid][p] = 0.f;
    __syncthreads();

    for (int p = tid; p < 64*80; p += 64) {
        int r = p / 80, c = p % 80;
        float v = sOut[r][c];
        __nv_bfloat16 h = __float2bfloat16(v);
        size_t o = (size_t)(n0 + r)*UDIM + c;
        uhg[o] = h;
        ulg[o] = __float2bfloat16(v - __bfloat162float(h));
    }
    __syncthreads();

    #pragma unroll
    for (int d = 0; d < 8; d++) sOut[tid][d] = km[d];
    #pragma unroll
    for (int d = 0; d < 8; d++)
        #pragma unroll
        for (int f = 0; f < 8; f++)
            sOut[tid][8 + d*8 + f] = km[d]*km[f];
    sOut[tid][72] = 1.0f;
    #pragma unroll
    for (int p = 73; p < 80; p++) sOut[tid][p] = 0.f;
    __syncthreads();

    for (int p = tid; p < 64*80; p += 64) {
        int r = p / 80, c = p % 80;
        float v = sOut[r][c];
        __nv_bfloat16 h = __float2bfloat16(v);
        size_t o = (size_t)(n0 + r)*UDIM + c;
        whg[o] = h;
        wlg[o] = __float2bfloat16(v - __bfloat162float(h));
    }
}

// ============================================================
// Tensor-core flash: S = U.W^T (bf16x3), P = exp(min(S,0)/temp)
// (S<=0 always, no max tracking), O = P.V (bf16x3), split-k over warp_n.
// 64x64 tiles, 8 warps; 2-stage cp.async, single sync per tile.
// ============================================================
#define FL_USTR 88
#define FL_VSTR 72
#define FL_OFF_UL (64*FL_USTR*2)            // 11264
#define FL_OFF_W  (2*64*FL_USTR*2)          // 22528
#define FL_WBUF   (2*64*FL_USTR*2)          // 22528
#define FL_OFF_V  (FL_OFF_W + 2*FL_WBUF)    // 67584
#define FL_VBUF   (2*64*FL_VSTR*2)          // 18432
#define FLASH_SMEM (FL_OFF_V + 2*FL_VBUF)   // 104448

__global__ __launch_bounds__(256, 1)
void flash_mma(const __nv_bfloat16* __restrict__ uh, const __nv_bfloat16* __restrict__ ul,
               const __nv_bfloat16* __restrict__ wh, const __nv_bfloat16* __restrict__ wl,
               const __nv_bfloat16* __restrict__ vh, const __nv_bfloat16* __restrict__ vl,
               __nv_bfloat16* __restrict__ oh, __nv_bfloat16* __restrict__ ol,
               const float* __restrict__ temperature)
{
    extern __shared__ char smem[];
    uint32_t sb = smem_u32(smem);
    int tid = threadIdx.x, wid = tid >> 5, lane = tid & 31;
    int warp_m = wid & 1, warp_n = wid >> 1;
    int bh = blockIdx.y;
    int ib = (int)(gridDim.x - 1 - blockIdx.x);
    float inv_temp = 1.f / fmaxf(temperature[0], 0.1f);

    // U tile load (joins first commit group)
    {
        const char* gh = (const char*)(uh + (size_t)(bh*SEQ + ib*64)*UDIM);
        const char* gl = (const char*)(ul + (size_t)(bh*SEQ + ib*64)*UDIM);
        for (int p = tid; p < 640; p += 256) {
            int r = p / 10, c = p % 10;
            CP_ASYNC16(sb + r*(FL_USTR*2) + c*16, gh + r*160 + c*16);
            CP_ASYNC16(sb + FL_OFF_UL + r*(FL_USTR*2) + c*16, gl + r*160 + c*16);
        }
    }
    #define ISSUE_WV(jb, buf) do { \
        const char* gwh = (const char*)(wh + (size_t)(bh*SEQ + (jb)*64)*UDIM); \
        const char* gwl = (const char*)(wl + (size_t)(bh*SEQ + (jb)*64)*UDIM); \
        uint32_t wdst = sb + FL_OFF_W + (buf)*FL_WBUF; \
        for (int p = tid; p < 640; p += 256) { \
            int r = p / 10, c = p % 10; \
            CP_ASYNC16(wdst + r*176 + c*16, gwh + r*160 + c*16); \
            CP_ASYNC16(wdst + 11264 + r*176 + c*16, gwl + r*160 + c*16); \
        } \
        const char* gvh = (const char*)(vh + (size_t)(bh*SEQ + (jb)*64)*DHEAD); \
        const char* gvl = (const char*)(vl + (size_t)(bh*SEQ + (jb)*64)*DHEAD); \
        uint32_t vdst = sb + FL_OFF_V + (buf)*FL_VBUF; \
        for (int p = tid; p < 512; p += 256) { \
            int r = p / 8, c = p % 8; \
            CP_ASYNC16(vdst + r*144 + c*16, gvh + r*128 + c*16); \
            CP_ASYNC16(vdst + 9216 + r*144 + c*16, gvl + r*128 + c*16); \
        } \
    } while (0)

    ISSUE_WV(0, 0);
    CP_COMMIT();

    float accO[2][8][4];
    float l_acc[4];
    #pragma unroll
    for (int i = 0; i < 4; i++) l_acc[i] = 0.f;
    #pragma unroll
    for (int mt = 0; mt < 2; mt++)
        #pragma unroll
        for (int nt = 0; nt < 8; nt++)
            #pragma unroll
            for (int r = 0; r < 4; r++) accO[mt][nt][r] = 0.f;

    for (int jb = 0; jb <= ib; jb++) {
        int buf = jb & 1;
        CP_WAIT(0);
        __syncthreads();           // data visible + protects buf^1 (computed last iter)
        if (jb < ib) { ISSUE_WV(jb+1, buf^1); CP_COMMIT(); }

        uint32_t sw_h = sb + FL_OFF_W + buf*FL_WBUF;
        uint32_t sw_l = sw_h + 11264;
        uint32_t sv_h = sb + FL_OFF_V + buf*FL_VBUF;
        uint32_t sv_l = sv_h + 9216;

        // ---- S = U . W^T ----
        float sc[2][2][4];
        #pragma unroll
        for (int mt = 0; mt < 2; mt++)
            #pragma unroll
            for (int nt = 0; nt < 2; nt++)
                #pragma unroll
                for (int r = 0; r < 4; r++) sc[mt][nt][r] = 0.f;

        #pragma unroll
        for (int k5 = 0; k5 < 5; k5++) {
            int k0 = k5*16;
            uint32_t a_h[2][4], a_l[2][4], b_h[2][2], b_l[2][2];
            #pragma unroll
            for (int mt = 0; mt < 2; mt++) {
                int row = warp_m*32 + mt*16 + (lane & 15);
                uint32_t off = (uint32_t)(row*FL_USTR + k0 + ((lane >> 4) << 3))*2;
                ldmatrix_x4(a_h[mt], sb + off);
                ldmatrix_x4(a_l[mt], sb + FL_OFF_UL + off);
            }
            #pragma unroll
            for (int nt = 0; nt < 2; nt++) {
                int row = warp_n*16 + nt*8 + (lane & 7);
                uint32_t off = (uint32_t)(row*FL_USTR + k0 + (((lane >> 3) & 1) << 3))*2;
                ldmatrix_x2(b_h[nt], sw_h + off);
                ldmatrix_x2(b_l[nt], sw_l + off);
            }
            #pragma unroll
            for (int mt = 0; mt < 2; mt++)
                #pragma unroll
                for (int nt = 0; nt < 2; nt++)
                    mma16816(sc[mt][nt], a_h[mt], b_h[nt]);
            #pragma unroll
            for (int mt = 0; mt < 2; mt++)
                #pragma unroll
                for (int nt = 0; nt < 2; nt++)
                    mma16816(sc[mt][nt], a_h[mt], b_l[nt]);
            #pragma unroll
            for (int mt = 0; mt < 2; mt++)
                #pragma unroll
                for (int nt = 0; nt < 2; nt++)
                    mma16816(sc[mt][nt], a_l[mt], b_h[nt]);
        }

        // ---- P = exp(min(S,0)/temp), causal mask, row-sum partials ----
        bool diag = (jb == ib);
        uint32_t ph[2][4], pl[2][4];
        #pragma unroll
        for (int mt = 0; mt < 2; mt++) {
            #pragma unroll
            for (int half = 0; half < 2; half++) {
                int t_g = ib*64 + warp_m*32 + mt*16 + (lane >> 2) + half*8;
                float pv[4];
                #pragma unroll
                for (int nt = 0; nt < 2; nt++) {
                    #pragma unroll
                    for (int cc = 0; cc < 2; cc++) {
                        int s_g = jb*64 + warp_n*16 + nt*8 + (lane & 3)*2 + cc;
                        float v = sc[mt][nt][half*2 + cc];
                        float p = __expf(fminf(v, 0.f) * inv_temp);
                        if (diag && s_g > t_g) p = 0.f;
                        pv[nt*2 + cc] = p;
                    }
                }
                float ls = pv[0] + pv[1] + pv[2] + pv[3];
                ls += __shfl_xor_sync(0xffffffffu, ls, 1);
                ls += __shfl_xor_sync(0xffffffffu, ls, 2);
                l_acc[mt*2 + half] += ls;
                split2(pv[0], pv[1], ph[mt][half], pl[mt][half]);
                split2(pv[2], pv[3], ph[mt][2 + half], pl[mt][2 + half]);
            }
        }

        // ---- O += P . V  (k-slice = warp_n's 16 s) ----
        #pragma unroll
        for (int ntp = 0; ntp < 4; ntp++) {
            uint32_t v_h[2][2], v_l[2][2];
            #pragma unroll
            for (int q2 = 0; q2 < 2; q2++) {
                int nt = ntp*2 + q2;
                uint32_t off = (uint32_t)((warp_n*16 + (lane & 15))*FL_VSTR + nt*8)*2;
                ldmatrix_x2_trans(v_h[q2], sv_h + off);
                ldmatrix_x2_trans(v_l[q2], sv_l + off);
            }
            #pragma unroll
            for (int mt = 0; mt < 2; mt++)
                #pragma unroll
                for (int q2 = 0; q2 < 2; q2++)
                    mma16816(accO[mt][ntp*2+q2], ph[mt], v_h[q2]);
            #pragma unroll
            for (int mt = 0; mt < 2; mt++)
                #pragma unroll
                for (int q2 = 0; q2 < 2; q2++)
                    mma16816(accO[mt][ntp*2+q2], ph[mt], v_l[q2]);
            #pragma unroll
            for (int mt = 0; mt < 2; mt++)
                #pragma unroll
                for (int q2 = 0; q2 < 2; q2++)
                    mma16816(accO[mt][ntp*2+q2], pl[mt], v_h[q2]);
        }
    }
    __syncthreads();   // last tile's ldmatrix done before smem reuse below

    // ---- cross-warp_n reduction (staged, reuses U region) ----
    float* sO   = (float*)smem;                 // [64][66]
    float* lred = (float*)(smem + 64*66*4);     // [64]
    #pragma unroll 1
    for (int stage = 0; stage < 4; stage++) {
        if (warp_n == stage) {
            #pragma unroll
            for (int mt = 0; mt < 2; mt++) {
                #pragma unroll
                for (int half = 0; half < 2; half++) {
                    int r = warp_m*32 + mt*16 + (lane >> 2) + half*8;
                    #pragma unroll
                    for (int nt = 0; nt < 8; nt++) {
                        int cc = nt*8 + (lane & 3)*2;
                        float v0 = accO[mt][nt][half*2 + 0];
                        float v1 = accO[mt][nt][half*2 + 1];
                        if (stage == 0) { sO[r*66+cc] = v0; sO[r*66+cc+1] = v1; }
                        else            { sO[r*66+cc] += v0; sO[r*66+cc+1] += v1; }
                    }
                    if ((lane & 3) == 0) {
                        if (stage == 0) lred[r] = l_acc[mt*2 + half];
                        else            lred[r] += l_acc[mt*2 + half];
                    }
                }
            }
        }
        __syncthreads();
    }

    // ---- normalize + write bf16 hi/lo token-major ----
    int b = bh >> 4, h = bh & 15;
    for (int p = tid; p < 4096; p += 256) {
        int t = p >> 6, d = p & 63;
        float v = sO[t*66 + d] / lred[t];
        __nv_bfloat16 hv = __float2bfloat16(v);
        size_t o = ((size_t)(b*SEQ + ib*64 + t))*DMODEL + h*64 + d;
        oh[o] = hv;
        ol[o] = __float2bfloat16(v - __bfloat162float(hv));
    }
}

// ============================================================
extern "C" void kernel_launch(void* const* d_in, const int* in_sizes, int n_in,
                              void* d_out, int out_size)
{
    (void)in_sizes; (void)n_in; (void)out_size;
    const float* x    = (const float*)d_in[0];
    const float* Wq   = (const float*)d_in[1];
    const float* Wk   = (const float*)d_in[2];
    const float* Wv   = (const float*)d_in[3];
    const float* Wo   = (const float*)d_in[4];
    const float* Wqm  = (const float*)d_in[5];
    const float* Wkm  = (const float*)d_in[6];
    const float* Wm   = (const float*)d_in[7];
    const float* temp = (const float*)d_in[8];

    float *q, *k, *ct, *st;
    __nv_bfloat16 *xh, *xl, *wth, *wtl, *vh, *vl, *uh, *ul, *wwh, *wwl, *a2h, *a2l;
    cudaGetSymbolAddress((void**)&q,   g_q);
    cudaGetSymbolAddress((void**)&k,   g_k);
    cudaGetSymbolAddress((void**)&ct,  g_cos);
    cudaGetSymbolAddress((void**)&st,  g_sin);
    cudaGetSymbolAddress((void**)&xh,  g_xh);
    cudaGetSymbolAddress((void**)&xl,  g_xl);
    cudaGetSymbolAddress((void**)&wth, g_wth);
    cudaGetSymbolAddress((void**)&wtl, g_wtl);
    cudaGetSymbolAddress((void**)&vh,  g_vh);
    cudaGetSymbolAddress((void**)&vl,  g_vl);
    cudaGetSymbolAddress((void**)&uh,  g_uh);
    cudaGetSymbolAddress((void**)&ul,  g_ul);
    cudaGetSymbolAddress((void**)&wwh, g_wh);
    cudaGetSymbolAddress((void**)&wwl, g_wl);
    cudaGetSymbolAddress((void**)&a2h, g_a2h);
    cudaGetSymbolAddress((void**)&a2l, g_a2l);

    cudaFuncSetAttribute(mma_gemm<0>, cudaFuncAttributeMaxDynamicSharedMemorySize, GEMM_SMEM);
    cudaFuncSetAttribute(mma_gemm<1>, cudaFuncAttributeMaxDynamicSharedMemorySize, GEMM_SMEM);
    cudaFuncSetAttribute(flash_mma,  cudaFuncAttributeMaxDynamicSharedMemorySize, FLASH_SMEM);

    rope_table_kernel<<<(SEQ*32)/256, 256>>>(ct, st);
    wconv_kernel<<<dim3(32, 32, 4), dim3(32, 8)>>>(Wq, Wk, Wv, Wo, wth, wtl);
    xconv_kernel<<<(NTOK*DMODEL)/256, 256>>>(x, xh, xl);

    // fused QKV (z=0 q, z=1 k f32 scatter; z=2 v bf16 hi/lo)
    size_t WSZ = (size_t)DMODEL*DMODEL;
    mma_gemm<1><<<dim3(DMODEL/64, NTOK/128, 3), 256, GEMM_SMEM>>>(
        xh, xl, wth, wtl, q, k, vh, vl);

    feature_kernel<<<NBHT/64, 64>>>(q, k, ct, st, Wqm, Wkm, Wm, uh, ul, wwh, wwl);

    flash_mma<<<dim3(SEQ/64, BATCH*NHEADS), 256, FLASH_SMEM>>>(
        uh, ul, wwh, wwl, vh, vl, a2h, a2l, temp);

    mma_gemm<0><<<dim3(DMODEL/64, NTOK/128, 1), 256, GEMM_SMEM>>>(
        a2h, a2l, wth + 3*WSZ, wtl + 3*WSZ, (float*)d_out,
        nullptr, nullptr, nullptr);
}

// round 7
// speedup vs baseline: 2.6138x; 1.0253x over previous
#include <cuda_runtime.h>
#include <cuda_bf16.h>
#include <math.h>
#include <stdint.h>

// Problem constants
#define BATCH   2
#define SEQ     1024
#define DMODEL  1024
#define NHEADS  16
#define DHEAD   64
#define NTOK    (BATCH*SEQ)          // 2048
#define NBHT    (BATCH*NHEADS*SEQ)   // 32768
#define UDIM    80                   // 73 padded to 80
#define EPS_PSD 0.001f

// -------- device scratch (static, no allocations) --------
__device__ float g_q[NBHT*DHEAD];
__device__ float g_k[NBHT*DHEAD];
__device__ float g_cos[SEQ*32];
__device__ float g_sin[SEQ*32];

__device__ __nv_bfloat16 g_xh[NTOK*DMODEL];
__device__ __nv_bfloat16 g_xl[NTOK*DMODEL];
__device__ __nv_bfloat16 g_wth[4*DMODEL*DMODEL]; // Wq,Wk,Wv,Wo transposed [n][k]
__device__ __nv_bfloat16 g_wtl[4*DMODEL*DMODEL];

__device__ __nv_bfloat16 g_vh[NBHT*DHEAD];       // V bf16 hi/lo [bh][t][d]
__device__ __nv_bfloat16 g_vl[NBHT*DHEAD];

__device__ __nv_bfloat16 g_uh[NBHT*UDIM];        // u rows bf16 hi/lo [n][80]
__device__ __nv_bfloat16 g_ul[NBHT*UDIM];
__device__ __nv_bfloat16 g_wh[NBHT*UDIM];        // w rows bf16 hi/lo [n][80]
__device__ __nv_bfloat16 g_wl[NBHT*UDIM];

__device__ __nv_bfloat16 g_a2h[NTOK*DMODEL];     // attention out, token-major
__device__ __nv_bfloat16 g_a2l[NTOK*DMODEL];

// ============================================================
// PTX helpers
// ============================================================
__device__ __forceinline__ uint32_t smem_u32(const void* p) {
    uint32_t a;
    asm("{ .reg .u64 t; cvta.to.shared.u64 t, %1; cvt.u32.u64 %0, t; }" : "=r"(a) : "l"(p));
    return a;
}
__device__ __forceinline__ void ldmatrix_x4(uint32_t* r, uint32_t addr) {
    asm volatile("ldmatrix.sync.aligned.m8n8.x4.shared.b16 {%0,%1,%2,%3}, [%4];"
        : "=r"(r[0]), "=r"(r[1]), "=r"(r[2]), "=r"(r[3]) : "r"(addr));
}
__device__ __forceinline__ void ldmatrix_x2(uint32_t* r, uint32_t addr) {
    asm volatile("ldmatrix.sync.aligned.m8n8.x2.shared.b16 {%0,%1}, [%2];"
        : "=r"(r[0]), "=r"(r[1]) : "r"(addr));
}
__device__ __forceinline__ void ldmatrix_x2_trans(uint32_t* r, uint32_t addr) {
    asm volatile("ldmatrix.sync.aligned.m8n8.x2.trans.shared.b16 {%0,%1}, [%2];"
        : "=r"(r[0]), "=r"(r[1]) : "r"(addr));
}
__device__ __forceinline__ void mma16816(float* c, const uint32_t* a, const uint32_t* b) {
    asm volatile("mma.sync.aligned.m16n8k16.row.col.f32.bf16.bf16.f32 "
        "{%0,%1,%2,%3}, {%4,%5,%6,%7}, {%8,%9}, {%0,%1,%2,%3};"
        : "+f"(c[0]), "+f"(c[1]), "+f"(c[2]), "+f"(c[3])
        : "r"(a[0]), "r"(a[1]), "r"(a[2]), "r"(a[3]), "r"(b[0]), "r"(b[1]));
}
#define CP_ASYNC16(saddr, gptr) \
    asm volatile("cp.async.cg.shared.global [%0], [%1], 16;" \
        :: "r"(saddr), "l"(gptr) : "memory")
#define CP_COMMIT() asm volatile("cp.async.commit_group;" ::: "memory")
#define CP_WAIT(N)  asm volatile("cp.async.wait_group %0;" :: "n"(N) : "memory")

__device__ __forceinline__ void split2(float v0, float v1, uint32_t& h, uint32_t& l) {
    __nv_bfloat16 h0 = __float2bfloat16(v0), h1 = __float2bfloat16(v1);
    __nv_bfloat162 hp; hp.x = h0; hp.y = h1;
    h = *(uint32_t*)&hp;
    __nv_bfloat16 l0 = __float2bfloat16(v0 - __bfloat162float(h0));
    __nv_bfloat16 l1 = __float2bfloat16(v1 - __bfloat162float(h1));
    __nv_bfloat162 lp; lp.x = l0; lp.y = l1;
    l = *(uint32_t*)&lp;
}

// ============================================================
// Conversion + table kernels
// ============================================================
__global__ void xconv_kernel(const float* __restrict__ x,
                             __nv_bfloat16* __restrict__ xh,
                             __nv_bfloat16* __restrict__ xl)
{
    int i = blockIdx.x * blockDim.x + threadIdx.x;
    if (i >= NTOK*DMODEL) return;
    float v = x[i];
    __nv_bfloat16 h = __float2bfloat16(v);
    xh[i] = h;
    xl[i] = __float2bfloat16(v - __bfloat162float(h));
}

__global__ void wconv_kernel(const float* __restrict__ W0, const float* __restrict__ W1,
                             const float* __restrict__ W2, const float* __restrict__ W3,
                             __nv_bfloat16* __restrict__ th, __nv_bfloat16* __restrict__ tl)
{
    __shared__ float s[32][33];
    const float* W = (blockIdx.z == 0) ? W0 : (blockIdx.z == 1) ? W1
                   : (blockIdx.z == 2) ? W2 : W3;
    size_t zoff = (size_t)blockIdx.z * DMODEL * DMODEL;
    int n0 = blockIdx.x * 32, k0 = blockIdx.y * 32;
    int tx = threadIdx.x, ty = threadIdx.y;   // 32 x 8
    #pragma unroll
    for (int j = 0; j < 4; j++)
        s[ty + j*8][tx] = W[(size_t)(k0 + ty + j*8)*DMODEL + n0 + tx];
    __syncthreads();
    #pragma unroll
    for (int j = 0; j < 4; j++) {
        float v = s[tx][ty + j*8];
        __nv_bfloat16 h = __float2bfloat16(v);
        size_t o = zoff + (size_t)(n0 + ty + j*8)*DMODEL + k0 + tx;
        th[o] = h;
        tl[o] = __float2bfloat16(v - __bfloat162float(h));
    }
}

__global__ void rope_table_kernel(float* __restrict__ ct, float* __restrict__ st)
{
    int idx = blockIdx.x * blockDim.x + threadIdx.x;
    if (idx >= SEQ*32) return;
    int i = idx & 31, t = idx >> 5;
    float inv = (float)(1.0 / pow(10000.0, (double)i / 32.0));
    float ang = (float)t * inv;
    float s, c;
    sincosf(ang, &s, &c);
    ct[idx] = c;
    st[idx] = s;
}

// ============================================================
// mma.sync bf16x3 GEMM, 128x128 CTA tile, 8 warps (2m x 4n),
// warp = 64x32 via 4x4 m16n8k16; B via ldmatrix.x4 (2 n-tiles/op);
// variant-outer order; 2-stage cp.async, single sync per chunk;
// __launch_bounds__(256,2) for 2 CTAs/SM.
// MODE 0: plain f32 out.  MODE 1: fused QKV (z: 0=q,1=k f32 scatter; 2=v bf16 hl).
// ============================================================
#define KC 32
#define ROW_STRIDE 40
#define MAT_BYTES (128*ROW_STRIDE*2)       // 10240
#define STAGE_BYTES (4*MAT_BYTES)          // 40960 (Ah, Al, Bh, Bl)
#define GEMM_SMEM (2*STAGE_BYTES)          // 81920

template<int MODE>
__global__ __launch_bounds__(256, 2)
void mma_gemm(const __nv_bfloat16* __restrict__ Ah, const __nv_bfloat16* __restrict__ Al,
              const __nv_bfloat16* __restrict__ Bh0, const __nv_bfloat16* __restrict__ Bl0,
              float* __restrict__ C0, float* __restrict__ C1,
              __nv_bfloat16* __restrict__ Cvh, __nv_bfloat16* __restrict__ Cvl)
{
    extern __shared__ char smem[];
    uint32_t sbase = smem_u32(smem);
    int tid = threadIdx.x, wid = tid >> 5, lane = tid & 31;
    int n0 = blockIdx.x * 128, m0 = blockIdx.y * 128;
    int z = (MODE == 1) ? blockIdx.z : 0;

    const __nv_bfloat16* Bh = Bh0 + (size_t)z * DMODEL * DMODEL;
    const __nv_bfloat16* Bl = Bl0 + (size_t)z * DMODEL * DMODEL;

    int mat = tid >> 6;        // 0=Ah 1=Al 2=Bh 3=Bl
    int tp  = tid & 63;
    const __nv_bfloat16* gsrc =
        (mat == 0) ? Ah + (size_t)m0*DMODEL :
        (mat == 1) ? Al + (size_t)m0*DMODEL :
        (mat == 2) ? Bh + (size_t)n0*DMODEL :
                     Bl + (size_t)n0*DMODEL;
    uint32_t moff = (uint32_t)mat * MAT_BYTES;

    int warp_m = wid & 1, warp_n = wid >> 1;

    float acc[4][4][4];
    #pragma unroll
    for (int a = 0; a < 4; a++)
        #pragma unroll
        for (int b = 0; b < 4; b++)
            #pragma unroll
            for (int c = 0; c < 4; c++) acc[a][b][c] = 0.f;

    #define GEMM_ISSUE(chunk, slot) do { \
        const __nv_bfloat16* g = gsrc + (chunk)*KC; \
        uint32_t sdst = sbase + (slot)*STAGE_BYTES + moff; \
        _Pragma("unroll") \
        for (int it = 0; it < 8; it++) { \
            int idx = tp + it*64; \
            int row = idx >> 2, c4 = idx & 3; \
            CP_ASYNC16(sdst + row*(ROW_STRIDE*2) + c4*16, \
                       g + (size_t)row*DMODEL + c4*8); \
        } \
        CP_COMMIT(); \
    } while (0)

    GEMM_ISSUE(0, 0);

    for (int c = 0; c < DMODEL/KC; c++) {
        int slot = c & 1;
        CP_WAIT(0);
        __syncthreads();                       // chunk c visible; slot^1 free of readers
        if (c + 1 < DMODEL/KC) GEMM_ISSUE(c + 1, slot ^ 1);

        uint32_t b_off = sbase + slot*STAGE_BYTES;
        #pragma unroll
        for (int ks = 0; ks < 2; ks++) {
            int k0 = ks * 16;
            uint32_t a_h[4][4], a_l[4][4], b_h[4][2], b_l[4][2];
            #pragma unroll
            for (int mt = 0; mt < 4; mt++) {
                int row = warp_m*64 + mt*16 + (lane & 15);
                uint32_t col = k0 + ((lane >> 4) << 3);
                uint32_t off = b_off + (row*ROW_STRIDE + col)*2;
                ldmatrix_x4(a_h[mt], off);
                ldmatrix_x4(a_l[mt], off + MAT_BYTES);
            }
            // B via x4: one op covers 2 n-tiles (16 rows, both k-halves)
            #pragma unroll
            for (int ntp = 0; ntp < 2; ntp++) {
                int row = warp_n*32 + ntp*16 + (lane & 7) + ((lane >> 4) << 3);
                uint32_t col = k0 + (((lane >> 3) & 1) << 3);
                uint32_t off = b_off + 2*MAT_BYTES + (row*ROW_STRIDE + col)*2;
                uint32_t rh[4], rl[4];
                ldmatrix_x4(rh, off);
                ldmatrix_x4(rl, off + MAT_BYTES);
                b_h[ntp*2+0][0] = rh[0]; b_h[ntp*2+0][1] = rh[1];
                b_h[ntp*2+1][0] = rh[2]; b_h[ntp*2+1][1] = rh[3];
                b_l[ntp*2+0][0] = rl[0]; b_l[ntp*2+0][1] = rl[1];
                b_l[ntp*2+1][0] = rl[2]; b_l[ntp*2+1][1] = rl[3];
            }
            #pragma unroll
            for (int mt = 0; mt < 4; mt++)
                #pragma unroll
                for (int nt = 0; nt < 4; nt++)
                    mma16816(acc[mt][nt], a_h[mt], b_h[nt]);
            #pragma unroll
            for (int mt = 0; mt < 4; mt++)
                #pragma unroll
                for (int nt = 0; nt < 4; nt++)
                    mma16816(acc[mt][nt], a_h[mt], b_l[nt]);
            #pragma unroll
            for (int mt = 0; mt < 4; mt++)
                #pragma unroll
                for (int nt = 0; nt < 4; nt++)
                    mma16816(acc[mt][nt], a_l[mt], b_h[nt]);
        }
    }

    // epilogue
    int qrow = lane >> 2, qcol = (lane & 3) * 2;
    #pragma unroll
    for (int mt = 0; mt < 4; mt++) {
        #pragma unroll
        for (int nt = 0; nt < 4; nt++) {
            int row0 = m0 + warp_m*64 + mt*16 + qrow;
            int col  = n0 + warp_n*32 + nt*8 + qcol;
            float2 v0 = make_float2(acc[mt][nt][0], acc[mt][nt][1]);
            float2 v1 = make_float2(acc[mt][nt][2], acc[mt][nt][3]);
            if (MODE == 0) {
                *(float2*)&C0[(size_t)row0*DMODEL + col] = v0;
                *(float2*)&C0[(size_t)(row0 + 8)*DMODEL + col] = v1;
            } else if (z < 2) {
                float* C = z ? C1 : C0;
                int h = col >> 6, d = col & 63;
                int b0 = row0 >> 10, t0 = row0 & 1023;
                *(float2*)&C[((size_t)((b0*NHEADS + h)*SEQ + t0))*DHEAD + d] = v0;
                int r1 = row0 + 8;
                int b1 = r1 >> 10, t1 = r1 & 1023;
                *(float2*)&C[((size_t)((b1*NHEADS + h)*SEQ + t1))*DHEAD + d] = v1;
            } else {
                int h = col >> 6, d = col & 63;
                #pragma unroll
                for (int rr = 0; rr < 2; rr++) {
                    int row = row0 + rr*8;
                    float2 v = rr ? v1 : v0;
                    int b = row >> 10, t = row & 1023;
                    size_t o = ((size_t)((b*NHEADS + h)*SEQ + t))*DHEAD + d;
                    __nv_bfloat16 h0 = __float2bfloat16(v.x), h1 = __float2bfloat16(v.y);
                    __nv_bfloat162 hp; hp.x = h0; hp.y = h1;
                    *(__nv_bfloat162*)&Cvh[o] = hp;
                    __nv_bfloat162 lp;
                    lp.x = __float2bfloat16(v.x - __bfloat162float(h0));
                    lp.y = __float2bfloat16(v.y - __bfloat162float(h1));
                    *(__nv_bfloat162*)&Cvl[o] = lp;
                }
            }
        }
    }
}

// ============================================================
// Feature kernel with fused RoPE -> bf16 hi/lo u and w rows [n][80]
// ============================================================
__global__ void feature_kernel(const float* __restrict__ q, const float* __restrict__ k,
                               const float* __restrict__ ct, const float* __restrict__ st,
                               const float* __restrict__ Wqm, const float* __restrict__ Wkm,
                               const float* __restrict__ Wm,
                               __nv_bfloat16* __restrict__ uhg, __nv_bfloat16* __restrict__ ulg,
                               __nv_bfloat16* __restrict__ whg, __nv_bfloat16* __restrict__ wlg)
{
    __shared__ float sWqm[512], sWkm[512], sWm[512];
    __shared__ float sOut[64][81];

    int tid = threadIdx.x;           // 64 threads
    int n0 = blockIdx.x * 64;
    int n  = n0 + tid;
    int t  = n & 1023;

    for (int p = tid; p < 512; p += 64) {
        sWqm[p] = Wqm[p]; sWkm[p] = Wkm[p]; sWm[p] = Wm[p];
    }
    __syncthreads();

    const float4* qr = (const float4*)(q + (size_t)n*64);
    const float4* kr = (const float4*)(k + (size_t)n*64);
    const float4* cp4 = (const float4*)(ct + (size_t)t*32);
    const float4* sp4 = (const float4*)(st + (size_t)t*32);

    float qm[8], km[8];
    #pragma unroll
    for (int m = 0; m < 8; m++) { qm[m] = 0.f; km[m] = 0.f; }
    #pragma unroll
    for (int d4 = 0; d4 < 8; d4++) {
        float4 q1 = qr[d4], q2 = qr[d4+8];
        float4 k1 = kr[d4], k2 = kr[d4+8];
        float4 cv = cp4[d4], sv = sp4[d4];
        const float* q1f = (const float*)&q1;
        const float* q2f = (const float*)&q2;
        const float* k1f = (const float*)&k1;
        const float* k2f = (const float*)&k2;
        const float* cf  = (const float*)&cv;
        const float* sf  = (const float*)&sv;
        #pragma unroll
        for (int j = 0; j < 4; j++) {
            int i = d4*4 + j;
            float c = cf[j], s = sf[j];
            float qa = q1f[j]*c - q2f[j]*s;
            float qb = q1f[j]*s + q2f[j]*c;
            float ka = k1f[j]*c - k2f[j]*s;
            float kb = k1f[j]*s + k2f[j]*c;
            #pragma unroll
            for (int m = 0; m < 8; m++) {
                qm[m] = fmaf(qa, sWqm[i*8+m], fmaf(qb, sWqm[(i+32)*8+m], qm[m]));
                km[m] = fmaf(ka, sWkm[i*8+m], fmaf(kb, sWkm[(i+32)*8+m], km[m]));
            }
        }
    }
    #pragma unroll
    for (int m = 0; m < 8; m++) {
        qm[m] = 1.0f / (1.0f + expf(-qm[m]));
        km[m] = 1.0f / (1.0f + expf(-km[m]));
    }

    float A[64];
    #pragma unroll
    for (int nn = 0; nn < 64; nn++) {
        float s = 0.f;
        #pragma unroll
        for (int m = 0; m < 8; m++) s = fmaf(qm[m], sWm[m*64+nn], s);
        A[nn] = s;
    }

    float Gq[8];
    #pragma unroll
    for (int d = 0; d < 8; d++) Gq[d] = 0.f;
    #pragma unroll
    for (int d = 0; d < 8; d++) {
        #pragma unroll
        for (int f = 0; f < 8; f++) {
            float g = 0.f;
            #pragma unroll
            for (int e = 0; e < 8; e++) g = fmaf(A[d*8+e], A[f*8+e], g);
            if (d == f) g += EPS_PSD;
            Gq[d] = fmaf(g, qm[f], Gq[d]);
            sOut[tid][8 + d*8 + f] = -g;
        }
    }
    float qGq = 0.f;
    #pragma unroll
    for (int d = 0; d < 8; d++) {
        qGq = fmaf(Gq[d], qm[d], qGq);
        sOut[tid][d] = 2.0f * Gq[d];
    }
    sOut[tid][72] = -qGq;
    #pragma unroll
    for (int p = 73; p < 80; p++) sOut[tid][p] = 0.f;
    __syncthreads();

    for (int p = tid; p < 64*80; p += 64) {
        int r = p / 80, c = p % 80;
        float v = sOut[r][c];
        __nv_bfloat16 h = __float2bfloat16(v);
        size_t o = (size_t)(n0 + r)*UDIM + c;
        uhg[o] = h;
        ulg[o] = __float2bfloat16(v - __bfloat162float(h));
    }
    __syncthreads();

    #pragma unroll
    for (int d = 0; d < 8; d++) sOut[tid][d] = km[d];
    #pragma unroll
    for (int d = 0; d < 8; d++)
        #pragma unroll
        for (int f = 0; f < 8; f++)
            sOut[tid][8 + d*8 + f] = km[d]*km[f];
    sOut[tid][72] = 1.0f;
    #pragma unroll
    for (int p = 73; p < 80; p++) sOut[tid][p] = 0.f;
    __syncthreads();

    for (int p = tid; p < 64*80; p += 64) {
        int r = p / 80, c = p % 80;
        float v = sOut[r][c];
        __nv_bfloat16 h = __float2bfloat16(v);
        size_t o = (size_t)(n0 + r)*UDIM + c;
        whg[o] = h;
        wlg[o] = __float2bfloat16(v - __bfloat162float(h));
    }
}

// ============================================================
// Tensor-core flash: S = U.W^T (bf16x3), P = exp(min(S,0)/temp)
// (S<=0 always, no max tracking), O = P.V (bf16x3), split-k over warp_n.
// 64x64 tiles, 8 warps; 2-stage cp.async, single sync per tile.
// ============================================================
#define FL_USTR 88
#define FL_VSTR 72
#define FL_OFF_UL (64*FL_USTR*2)            // 11264
#define FL_OFF_W  (2*64*FL_USTR*2)          // 22528
#define FL_WBUF   (2*64*FL_USTR*2)          // 22528
#define FL_OFF_V  (FL_OFF_W + 2*FL_WBUF)    // 67584
#define FL_VBUF   (2*64*FL_VSTR*2)          // 18432
#define FLASH_SMEM (FL_OFF_V + 2*FL_VBUF)   // 104448

__global__ __launch_bounds__(256, 1)
void flash_mma(const __nv_bfloat16* __restrict__ uh, const __nv_bfloat16* __restrict__ ul,
               const __nv_bfloat16* __restrict__ wh, const __nv_bfloat16* __restrict__ wl,
               const __nv_bfloat16* __restrict__ vh, const __nv_bfloat16* __restrict__ vl,
               __nv_bfloat16* __restrict__ oh, __nv_bfloat16* __restrict__ ol,
               const float* __restrict__ temperature)
{
    extern __shared__ char smem[];
    uint32_t sb = smem_u32(smem);
    int tid = threadIdx.x, wid = tid >> 5, lane = tid & 31;
    int warp_m = wid & 1, warp_n = wid >> 1;
    int bh = blockIdx.y;
    int ib = (int)(gridDim.x - 1 - blockIdx.x);
    float inv_temp = 1.f / fmaxf(temperature[0], 0.1f);

    // U tile load (joins first commit group)
    {
        const char* gh = (const char*)(uh + (size_t)(bh*SEQ + ib*64)*UDIM);
        const char* gl = (const char*)(ul + (size_t)(bh*SEQ + ib*64)*UDIM);
        for (int p = tid; p < 640; p += 256) {
            int r = p / 10, c = p % 10;
            CP_ASYNC16(sb + r*(FL_USTR*2) + c*16, gh + r*160 + c*16);
            CP_ASYNC16(sb + FL_OFF_UL + r*(FL_USTR*2) + c*16, gl + r*160 + c*16);
        }
    }
    #define ISSUE_WV(jb, buf) do { \
        const char* gwh = (const char*)(wh + (size_t)(bh*SEQ + (jb)*64)*UDIM); \
        const char* gwl = (const char*)(wl + (size_t)(bh*SEQ + (jb)*64)*UDIM); \
        uint32_t wdst = sb + FL_OFF_W + (buf)*FL_WBUF; \
        for (int p = tid; p < 640; p += 256) { \
            int r = p / 10, c = p % 10; \
            CP_ASYNC16(wdst + r*176 + c*16, gwh + r*160 + c*16); \
            CP_ASYNC16(wdst + 11264 + r*176 + c*16, gwl + r*160 + c*16); \
        } \
        const char* gvh = (const char*)(vh + (size_t)(bh*SEQ + (jb)*64)*DHEAD); \
        const char* gvl = (const char*)(vl + (size_t)(bh*SEQ + (jb)*64)*DHEAD); \
        uint32_t vdst = sb + FL_OFF_V + (buf)*FL_VBUF; \
        for (int p = tid; p < 512; p += 256) { \
            int r = p / 8, c = p % 8; \
            CP_ASYNC16(vdst + r*144 + c*16, gvh + r*128 + c*16); \
            CP_ASYNC16(vdst + 9216 + r*144 + c*16, gvl + r*128 + c*16); \
        } \
    } while (0)

    ISSUE_WV(0, 0);
    CP_COMMIT();

    float accO[2][8][4];
    float l_acc[4];
    #pragma unroll
    for (int i = 0; i < 4; i++) l_acc[i] = 0.f;
    #pragma unroll
    for (int mt = 0; mt < 2; mt++)
        #pragma unroll
        for (int nt = 0; nt < 8; nt++)
            #pragma unroll
            for (int r = 0; r < 4; r++) accO[mt][nt][r] = 0.f;

    for (int jb = 0; jb <= ib; jb++) {
        int buf = jb & 1;
        CP_WAIT(0);
        __syncthreads();           // data visible + protects buf^1 (computed last iter)
        if (jb < ib) { ISSUE_WV(jb+1, buf^1); CP_COMMIT(); }

        uint32_t sw_h = sb + FL_OFF_W + buf*FL_WBUF;
        uint32_t sw_l = sw_h + 11264;
        uint32_t sv_h = sb + FL_OFF_V + buf*FL_VBUF;
        uint32_t sv_l = sv_h + 9216;

        // ---- S = U . W^T ----
        float sc[2][2][4];
        #pragma unroll
        for (int mt = 0; mt < 2; mt++)
            #pragma unroll
            for (int nt = 0; nt < 2; nt++)
                #pragma unroll
                for (int r = 0; r < 4; r++) sc[mt][nt][r] = 0.f;

        #pragma unroll
        for (int k5 = 0; k5 < 5; k5++) {
            int k0 = k5*16;
            uint32_t a_h[2][4], a_l[2][4], b_h[2][2], b_l[2][2];
            #pragma unroll
            for (int mt = 0; mt < 2; mt++) {
                int row = warp_m*32 + mt*16 + (lane & 15);
                uint32_t off = (uint32_t)(row*FL_USTR + k0 + ((lane >> 4) << 3))*2;
                ldmatrix_x4(a_h[mt], sb + off);
                ldmatrix_x4(a_l[mt], sb + FL_OFF_UL + off);
            }
            #pragma unroll
            for (int nt = 0; nt < 2; nt++) {
                int row = warp_n*16 + nt*8 + (lane & 7);
                uint32_t off = (uint32_t)(row*FL_USTR + k0 + (((lane >> 3) & 1) << 3))*2;
                ldmatrix_x2(b_h[nt], sw_h + off);
                ldmatrix_x2(b_l[nt], sw_l + off);
            }
            #pragma unroll
            for (int mt = 0; mt < 2; mt++)
                #pragma unroll
                for (int nt = 0; nt < 2; nt++)
                    mma16816(sc[mt][nt], a_h[mt], b_h[nt]);
            #pragma unroll
            for (int mt = 0; mt < 2; mt++)
                #pragma unroll
                for (int nt = 0; nt < 2; nt++)
                    mma16816(sc[mt][nt], a_h[mt], b_l[nt]);
            #pragma unroll
            for (int mt = 0; mt < 2; mt++)
                #pragma unroll
                for (int nt = 0; nt < 2; nt++)
                    mma16816(sc[mt][nt], a_l[mt], b_h[nt]);
        }

        // ---- P = exp(min(S,0)/temp), causal mask, row-sum partials ----
        bool diag = (jb == ib);
        uint32_t ph[2][4], pl[2][4];
        #pragma unroll
        for (int mt = 0; mt < 2; mt++) {
            #pragma unroll
            for (int half = 0; half < 2; half++) {
                int t_g = ib*64 + warp_m*32 + mt*16 + (lane >> 2) + half*8;
                float pv[4];
                #pragma unroll
                for (int nt = 0; nt < 2; nt++) {
                    #pragma unroll
                    for (int cc = 0; cc < 2; cc++) {
                        int s_g = jb*64 + warp_n*16 + nt*8 + (lane & 3)*2 + cc;
                        float v = sc[mt][nt][half*2 + cc];
                        float p = __expf(fminf(v, 0.f) * inv_temp);
                        if (diag && s_g > t_g) p = 0.f;
                        pv[nt*2 + cc] = p;
                    }
                }
                float ls = pv[0] + pv[1] + pv[2] + pv[3];
                ls += __shfl_xor_sync(0xffffffffu, ls, 1);
                ls += __shfl_xor_sync(0xffffffffu, ls, 2);
                l_acc[mt*2 + half] += ls;
                split2(pv[0], pv[1], ph[mt][half], pl[mt][half]);
                split2(pv[2], pv[3], ph[mt][2 + half], pl[mt][2 + half]);
            }
        }

        // ---- O += P . V  (k-slice = warp_n's 16 s) ----
        #pragma unroll
        for (int ntp = 0; ntp < 4; ntp++) {
            uint32_t v_h[2][2], v_l[2][2];
            #pragma unroll
            for (int q2 = 0; q2 < 2; q2++) {
                int nt = ntp*2 + q2;
                uint32_t off = (uint32_t)((warp_n*16 + (lane & 15))*FL_VSTR + nt*8)*2;
                ldmatrix_x2_trans(v_h[q2], sv_h + off);
                ldmatrix_x2_trans(v_l[q2], sv_l + off);
            }
            #pragma unroll
            for (int mt = 0; mt < 2; mt++)
                #pragma unroll
                for (int q2 = 0; q2 < 2; q2++)
                    mma16816(accO[mt][ntp*2+q2], ph[mt], v_h[q2]);
            #pragma unroll
            for (int mt = 0; mt < 2; mt++)
                #pragma unroll
                for (int q2 = 0; q2 < 2; q2++)
                    mma16816(accO[mt][ntp*2+q2], ph[mt], v_l[q2]);
            #pragma unroll
            for (int mt = 0; mt < 2; mt++)
                #pragma unroll
                for (int q2 = 0; q2 < 2; q2++)
                    mma16816(accO[mt][ntp*2+q2], pl[mt], v_h[q2]);
        }
    }
    __syncthreads();   // last tile's ldmatrix done before smem reuse below

    // ---- cross-warp_n reduction (staged, reuses U region) ----
    float* sO   = (float*)smem;                 // [64][66]
    float* lred = (float*)(smem + 64*66*4);     // [64]
    #pragma unroll 1
    for (int stage = 0; stage < 4; stage++) {
        if (warp_n == stage) {
            #pragma unroll
            for (int mt = 0; mt < 2; mt++) {
                #pragma unroll
                for (int half = 0; half < 2; half++) {
                    int r = warp_m*32 + mt*16 + (lane >> 2) + half*8;
                    #pragma unroll
                    for (int nt = 0; nt < 8; nt++) {
                        int cc = nt*8 + (lane & 3)*2;
                        float v0 = accO[mt][nt][half*2 + 0];
                        float v1 = accO[mt][nt][half*2 + 1];
                        if (stage == 0) { sO[r*66+cc] = v0; sO[r*66+cc+1] = v1; }
                        else            { sO[r*66+cc] += v0; sO[r*66+cc+1] += v1; }
                    }
                    if ((lane & 3) == 0) {
                        if (stage == 0) lred[r] = l_acc[mt*2 + half];
                        else            lred[r] += l_acc[mt*2 + half];
                    }
                }
            }
        }
        __syncthreads();
    }

    // ---- normalize + write bf16 hi/lo token-major ----
    int b = bh >> 4, h = bh & 15;
    for (int p = tid; p < 4096; p += 256) {
        int t = p >> 6, d = p & 63;
        float v = sO[t*66 + d] / lred[t];
        __nv_bfloat16 hv = __float2bfloat16(v);
        size_t o = ((size_t)(b*SEQ + ib*64 + t))*DMODEL + h*64 + d;
        oh[o] = hv;
        ol[o] = __float2bfloat16(v - __bfloat162float(hv));
    }
}

// ============================================================
extern "C" void kernel_launch(void* const* d_in, const int* in_sizes, int n_in,
                              void* d_out, int out_size)
{
    (void)in_sizes; (void)n_in; (void)out_size;
    const float* x    = (const float*)d_in[0];
    const float* Wq   = (const float*)d_in[1];
    const float* Wk   = (const float*)d_in[2];
    const float* Wv   = (const float*)d_in[3];
    const float* Wo   = (const float*)d_in[4];
    const float* Wqm  = (const float*)d_in[5];
    const float* Wkm  = (const float*)d_in[6];
    const float* Wm   = (const float*)d_in[7];
    const float* temp = (const float*)d_in[8];

    float *q, *k, *ct, *st;
    __nv_bfloat16 *xh, *xl, *wth, *wtl, *vh, *vl, *uh, *ul, *wwh, *wwl, *a2h, *a2l;
    cudaGetSymbolAddress((void**)&q,   g_q);
    cudaGetSymbolAddress((void**)&k,   g_k);
    cudaGetSymbolAddress((void**)&ct,  g_cos);
    cudaGetSymbolAddress((void**)&st,  g_sin);
    cudaGetSymbolAddress((void**)&xh,  g_xh);
    cudaGetSymbolAddress((void**)&xl,  g_xl);
    cudaGetSymbolAddress((void**)&wth, g_wth);
    cudaGetSymbolAddress((void**)&wtl, g_wtl);
    cudaGetSymbolAddress((void**)&vh,  g_vh);
    cudaGetSymbolAddress((void**)&vl,  g_vl);
    cudaGetSymbolAddress((void**)&uh,  g_uh);
    cudaGetSymbolAddress((void**)&ul,  g_ul);
    cudaGetSymbolAddress((void**)&wwh, g_wh);
    cudaGetSymbolAddress((void**)&wwl, g_wl);
    cudaGetSymbolAddress((void**)&a2h, g_a2h);
    cudaGetSymbolAddress((void**)&a2l, g_a2l);

    cudaFuncSetAttribute(mma_gemm<0>, cudaFuncAttributeMaxDynamicSharedMemorySize, GEMM_SMEM);
    cudaFuncSetAttribute(mma_gemm<1>, cudaFuncAttributeMaxDynamicSharedMemorySize, GEMM_SMEM);
    cudaFuncSetAttribute(flash_mma,  cudaFuncAttributeMaxDynamicSharedMemorySize, FLASH_SMEM);

    rope_table_kernel<<<(SEQ*32)/256, 256>>>(ct, st);
    wconv_kernel<<<dim3(32, 32, 4), dim3(32, 8)>>>(Wq, Wk, Wv, Wo, wth, wtl);
    xconv_kernel<<<(NTOK*DMODEL)/256, 256>>>(x, xh, xl);

    // fused QKV (z=0 q, z=1 k f32 scatter; z=2 v bf16 hi/lo)
    size_t WSZ = (size_t)DMODEL*DMODEL;
    mma_gemm<1><<<dim3(DMODEL/128, NTOK/128, 3), 256, GEMM_SMEM>>>(
        xh, xl, wth, wtl, q, k, vh, vl);

    feature_kernel<<<NBHT/64, 64>>>(q, k, ct, st, Wqm, Wkm, Wm, uh, ul, wwh, wwl);

    flash_mma<<<dim3(SEQ/64, BATCH*NHEADS), 256, FLASH_SMEM>>>(
        uh, ul, wwh, wwl, vh, vl, a2h, a2l, temp);

    mma_gemm<0><<<dim3(DMODEL/128, NTOK/128, 1), 256, GEMM_SMEM>>>(
        a2h, a2l, wth + 3*WSZ, wtl + 3*WSZ, (float*)d_out,
        nullptr, nullptr, nullptr);
}